// round 1
// baseline (speedup 1.0000x reference)
#include <cuda_runtime.h>
#include <math.h>

#define R_    2048
#define NODE_ 53
#define H_    512
#define C_    51
#define NOBJ_ 151
#define OUT_  512
#define T_    3
#define RN_   (R_*NODE_)      /* 108544 */
#define K2_   (NODE_*OUT_)    /* 27136  */
#define SPLITS_ 32
#define KSLICE_ (K2_/SPLITS_) /* 848 */

// ---------------- scratch (device globals; no allocation in kernel_launch) ----
__device__ float g_hidden[RN_*H_];        // (RN, 512) fh
__device__ float g_av    [RN_*H_];        // (RN, 512) av_half
__device__ float g_zr    [RN_*1024];      // (RN, 1024) [zv | rv]
__device__ float g_hv    [RN_*H_];        // (RN, 512)
__device__ float g_out   [RN_*OUT_];      // (RN, 512) relu output
__device__ float g_weff  [3*H_*H_];       // folded W (w3w,w4w,w5w halves summed), rows: [W3e;W4e;W5e]
__device__ float g_ucat  [3*H_*H_];       // [w3u;w4u;w5u]
__device__ float g_bias  [3*H_];          // [b3w+b3u; b4w+b4u; b5w+b5u]
__device__ float g_row   [R_*C_];
__device__ float g_part  [SPLITS_*R_*C_]; // split-K partials for final GEMM

// ---------------- prep kernels ------------------------------------------------
__global__ void k_prep_row(const int* __restrict__ sop, const float* __restrict__ matrix) {
    int i = blockIdx.x*blockDim.x + threadIdx.x;
    if (i >= R_*C_) return;
    int r = i / C_, c = i - r*C_;
    int s0 = sop[2*r], s1 = sop[2*r+1];
    g_row[i] = matrix[((size_t)s0*NOBJ_ + s1)*C_ + c];
}

__global__ void k_prep_w(const float* w3w, const float* w3u, const float* b3w, const float* b3u,
                         const float* w4w, const float* w4u, const float* b4w, const float* b4u,
                         const float* w5w, const float* w5u, const float* b5w, const float* b5u) {
    int i = blockIdx.x*blockDim.x + threadIdx.x;
    if (i < 3*H_*H_) {
        int g = i / (H_*H_);
        int rem = i - g*(H_*H_);
        int h = rem / H_, k = rem - h*H_;
        const float* ww = (g==0) ? w3w : (g==1) ? w4w : w5w;
        const float* wu = (g==0) ? w3u : (g==1) ? w4u : w5u;
        g_weff[i] = ww[h*(2*H_) + k] + ww[h*(2*H_) + H_ + k];  // fold concat([av,av],-1)
        g_ucat[i] = wu[rem];
    }
    if (i < 3*H_) {
        int g = i / H_, h = i - g*H_;
        const float* bw = (g==0) ? b3w : (g==1) ? b4w : b5w;
        const float* bu = (g==0) ? b3u : (g==1) ? b4u : b5u;
        g_bias[i] = bw[h] + bu[h];
    }
}

__global__ void k_copy_in(const float* __restrict__ src) {
    int n4 = (RN_*H_)/4;
    for (int i = blockIdx.x*blockDim.x + threadIdx.x; i < n4; i += gridDim.x*blockDim.x)
        ((float4*)g_hidden)[i] = ((const float4*)src)[i];
}

// ---------------- av computation ----------------------------------------------
// av[r,0]=av[r,1]=sum_c row[r,c]*hid[r,2+c];  av[r,2+c]=row[r,c]*(hid[r,0]+hid[r,1])
__global__ void k_av() {
    __shared__ float srow[C_];
    int r = blockIdx.y;
    if (threadIdx.x < C_) srow[threadIdx.x] = g_row[r*C_ + threadIdx.x];
    __syncthreads();
    int h = blockIdx.x*blockDim.x + threadIdx.x;    // grid.x=2, blockDim=256 -> h<512 always
    const float* hb = g_hidden + (size_t)r*NODE_*H_;
    float*       ab = g_av     + (size_t)r*NODE_*H_;
    float s01 = hb[h] + hb[H_ + h];
    float acc = 0.f;
    #pragma unroll 3
    for (int c = 0; c < C_; ++c) {
        float rc = srow[c];
        acc = fmaf(rc, hb[(2+c)*H_ + h], acc);
        ab[(2+c)*H_ + h] = rc * s01;
    }
    ab[h]      = acc;
    ab[H_ + h] = acc;
}

// ---------------- GRU elementwise update ---------------------------------------
__global__ void k_update() {
    int i = blockIdx.x*blockDim.x + threadIdx.x;
    if (i >= RN_*H_) return;
    int m = i >> 9, h = i & (H_-1);
    float z = g_zr[(size_t)m*1024 + h];
    float f = g_hidden[i];
    g_hidden[i] = (1.f - z)*f + z*g_hv[i];
}

// ---------------- generic fused dual-GEMM --------------------------------------
// C[m,n] = act( sum_k A1[m,k]W1[n,k]  (+ sum_k (A2[m,k]*A2m[m,k]?)W2[n,k])  + bias[n] )
// BM=128, BN=64, BK=16, 256 threads, 8x4 per thread. M%128==0, K%16==0 assumed.
#define ACT_NONE 0
#define ACT_SIG  1
#define ACT_TANH 2
#define ACT_RELU 3

template<int ACT, bool DUAL, bool MUL2, bool SPLITK>
__global__ void __launch_bounds__(256) k_gemm(
    const float* __restrict__ A1, int lda1, const float* __restrict__ W1, int ldw1,
    const float* __restrict__ A2, int lda2, const float* __restrict__ W2, int ldw2,
    const float* __restrict__ A2m, int ldm,
    const float* __restrict__ bias,
    float* __restrict__ Co, int ldc,
    int M, int N, int K)
{
    __shared__ __align__(16) float As[16][128];
    __shared__ __align__(16) float Ws[16][64];

    const int tx = threadIdx.x & 15;   // N dir (4 cols each)
    const int ty = threadIdx.x >> 4;   // M dir (8 rows each)
    const int blockRow = blockIdx.y * 128;
    const int blockCol = blockIdx.x * 64;

    int kbeg = 0, kend = K;
    if (SPLITK) { kbeg = blockIdx.z * KSLICE_; kend = kbeg + KSLICE_; }

    float acc[8][4];
    #pragma unroll
    for (int i = 0; i < 8; ++i)
        #pragma unroll
        for (int j = 0; j < 4; ++j) acc[i][j] = 0.f;

    const int nterms = DUAL ? 2 : 1;
    for (int term = 0; term < nterms; ++term) {
        const float* A  = term ? A2  : A1;  const int lda = term ? lda2 : lda1;
        const float* W  = term ? W2  : W1;  const int ldw = term ? ldw2 : ldw1;

        for (int k0 = kbeg; k0 < kend; k0 += 16) {
            // load A tile (128x16) transposed into As[k][m]
            #pragma unroll
            for (int t = 0; t < 2; ++t) {
                int l  = threadIdx.x + t*256;     // float4 id in [0,512)
                int m  = l >> 2;
                int kv = (l & 3) << 2;
                float4 v = *(const float4*)&A[(size_t)(blockRow + m)*lda + k0 + kv];
                if (MUL2 && term == 1) {
                    float4 mu = *(const float4*)&A2m[(size_t)(blockRow + m)*ldm + k0 + kv];
                    v.x *= mu.x; v.y *= mu.y; v.z *= mu.z; v.w *= mu.w;
                }
                As[kv+0][m] = v.x; As[kv+1][m] = v.y; As[kv+2][m] = v.z; As[kv+3][m] = v.w;
            }
            // load W tile (64x16) into Ws[k][n]
            {
                int n  = threadIdx.x >> 2;
                int kv = (threadIdx.x & 3) << 2;
                int gn = blockCol + n;
                float4 v = make_float4(0.f,0.f,0.f,0.f);
                if (gn < N) v = *(const float4*)&W[(size_t)gn*ldw + k0 + kv];
                Ws[kv+0][n] = v.x; Ws[kv+1][n] = v.y; Ws[kv+2][n] = v.z; Ws[kv+3][n] = v.w;
            }
            __syncthreads();
            #pragma unroll
            for (int kk = 0; kk < 16; ++kk) {
                float a[8], b[4];
                *(float4*)&a[0] = *(const float4*)&As[kk][ty*8];
                *(float4*)&a[4] = *(const float4*)&As[kk][ty*8+4];
                *(float4*)&b[0] = *(const float4*)&Ws[kk][tx*4];
                #pragma unroll
                for (int i = 0; i < 8; ++i)
                    #pragma unroll
                    for (int j = 0; j < 4; ++j)
                        acc[i][j] = fmaf(a[i], b[j], acc[i][j]);
            }
            __syncthreads();
        }
    }

    size_t outBase = SPLITK ? (size_t)blockIdx.z * (size_t)M * ldc : 0;
    #pragma unroll
    for (int i = 0; i < 8; ++i) {
        int gm = blockRow + ty*8 + i;
        #pragma unroll
        for (int j = 0; j < 4; ++j) {
            int gn = blockCol + tx*4 + j;
            if (gn < N) {
                float v = acc[i][j];
                if (!SPLITK) v += bias[gn];
                if (ACT == ACT_SIG)       v = 1.f / (1.f + __expf(-v));
                else if (ACT == ACT_TANH) v = tanhf(v);
                else if (ACT == ACT_RELU) v = fmaxf(v, 0.f);
                Co[outBase + (size_t)gm*ldc + gn] = v;
            }
        }
    }
}

// ---------------- split-K reduce -----------------------------------------------
__global__ void k_reduce(const float* __restrict__ bc, float* __restrict__ out) {
    int i = blockIdx.x*blockDim.x + threadIdx.x;
    if (i >= R_*C_) return;
    float s = bc[i % C_];
    #pragma unroll
    for (int z = 0; z < SPLITS_; ++z) s += g_part[(size_t)z*R_*C_ + i];
    out[i] = s;
}

// ---------------- launch -------------------------------------------------------
extern "C" void kernel_launch(void* const* d_in, const int* in_sizes, int n_in,
                              void* d_out, int out_size) {
    const int*   sop    = (const int*)  d_in[1];
    const float* input  = (const float*)d_in[2];
    const float* matrix = (const float*)d_in[4];
    const float* w3w = (const float*)d_in[5];  const float* b3w = (const float*)d_in[6];
    const float* w3u = (const float*)d_in[7];  const float* b3u = (const float*)d_in[8];
    const float* w4w = (const float*)d_in[9];  const float* b4w = (const float*)d_in[10];
    const float* w4u = (const float*)d_in[11]; const float* b4u = (const float*)d_in[12];
    const float* w5w = (const float*)d_in[13]; const float* b5w = (const float*)d_in[14];
    const float* w5u = (const float*)d_in[15]; const float* b5u = (const float*)d_in[16];
    const float* wo  = (const float*)d_in[17]; const float* bo  = (const float*)d_in[18];
    const float* wc  = (const float*)d_in[19]; const float* bc  = (const float*)d_in[20];
    float* out = (float*)d_out;

    float *p_hidden, *p_av, *p_zr, *p_hv, *p_out, *p_weff, *p_ucat, *p_bias, *p_part;
    cudaGetSymbolAddress((void**)&p_hidden, g_hidden);
    cudaGetSymbolAddress((void**)&p_av,     g_av);
    cudaGetSymbolAddress((void**)&p_zr,     g_zr);
    cudaGetSymbolAddress((void**)&p_hv,     g_hv);
    cudaGetSymbolAddress((void**)&p_out,    g_out);
    cudaGetSymbolAddress((void**)&p_weff,   g_weff);
    cudaGetSymbolAddress((void**)&p_ucat,   g_ucat);
    cudaGetSymbolAddress((void**)&p_bias,   g_bias);
    cudaGetSymbolAddress((void**)&p_part,   g_part);

    // prep
    k_prep_row<<<(R_*C_ + 255)/256, 256>>>(sop, matrix);
    k_prep_w<<<(3*H_*H_ + 255)/256, 256>>>(w3w, w3u, b3w, b3u,
                                           w4w, w4u, b4w, b4u,
                                           w5w, w5u, b5w, b5u);
    k_copy_in<<<4096, 256>>>(input);

    dim3 gGate(1024/64, RN_/128);   // zv|rv : N=1024
    dim3 gHv  (512/64,  RN_/128);   // hv    : N=512
    dim3 gOut (512/64,  RN_/128);   // relu out

    for (int t = 0; t < T_; ++t) {
        k_av<<<dim3(2, R_), 256>>>();
        // [zv|rv] = sigmoid(av@[W3e;W4e].T + fh@[w3u;w4u].T + bias)
        k_gemm<ACT_SIG, true, false, false><<<gGate, 256>>>(
            p_av, H_, p_weff, H_,
            p_hidden, H_, p_ucat, H_,
            nullptr, 0, p_bias, p_zr, 1024, RN_, 1024, H_);
        // hv = tanh(av@W5e.T + (rv*fh)@w5u.T + bias5)
        k_gemm<ACT_TANH, true, true, false><<<gHv, 256>>>(
            p_av, H_, p_weff + 2*H_*H_, H_,
            p_hidden, H_, p_ucat + 2*H_*H_, H_,
            p_zr + H_, 1024, p_bias + 2*H_, p_hv, H_, RN_, H_, H_);
        k_update<<<(RN_*H_ + 255)/256, 256>>>();
    }

    // out = relu(fh@wo[:, :H].T + input@wo[:, H:].T + bo)
    k_gemm<ACT_RELU, true, false, false><<<gOut, 256>>>(
        p_hidden, H_, wo, 2*H_,
        input, H_, wo + H_, 2*H_,
        nullptr, 0, bo, p_out, OUT_, RN_, OUT_, H_);

    // rel_dists = out.reshape(R, 27136) @ wc.T + bc  (split-K=32)
    k_gemm<ACT_NONE, false, false, true><<<dim3(1, R_/128, SPLITS_), 256>>>(
        p_out, K2_, wc, K2_,
        nullptr, 0, nullptr, 0,
        nullptr, 0, nullptr, p_part, C_, R_, C_, K2_);
    k_reduce<<<(R_*C_ + 255)/256, 256>>>(bc, out);
}

// round 3
// speedup vs baseline: 1.7644x; 1.7644x over previous
#include <cuda_runtime.h>
#include <math.h>
#include <stdint.h>

#define R_    2048
#define NODE_ 53
#define H_    512
#define C_    51
#define NOBJ_ 151
#define OUT_  512
#define T_    3
#define RN_   (R_*NODE_)      /* 108544 */
#define K2_   (NODE_*OUT_)    /* 27136  */
#define SPLITS_ 32
#define KSLICE_ (K2_/SPLITS_) /* 848 */

// ================= scratch =================
__device__ float g_hid0 [RN_*H_];
__device__ float g_hid1 [RN_*H_];
__device__ float g_av   [RN_*H_];
__device__ float g_zr   [RN_*1024];
__device__ float g_out  [RN_*OUT_];
__device__ float g_weff [3*H_*H_];
__device__ float g_ucat [3*H_*H_];
__device__ float g_bias [3*H_];
__device__ float g_row  [R_*C_];
__device__ float g_part [SPLITS_*R_*C_];

// ================= prep =================
__global__ void k_prep_row(const int* __restrict__ sop, const float* __restrict__ matrix) {
    int i = blockIdx.x*blockDim.x + threadIdx.x;
    if (i >= R_*C_) return;
    int r = i / C_, c = i - r*C_;
    g_row[i] = matrix[((size_t)sop[2*r]*NOBJ_ + sop[2*r+1])*C_ + c];
}

__global__ void k_prep_w(const float* w3w, const float* w3u, const float* b3w, const float* b3u,
                         const float* w4w, const float* w4u, const float* b4w, const float* b4u,
                         const float* w5w, const float* w5u, const float* b5w, const float* b5u) {
    int i = blockIdx.x*blockDim.x + threadIdx.x;
    if (i < 3*H_*H_) {
        int g = i / (H_*H_);
        int rem = i - g*(H_*H_);
        int h = rem / H_, k = rem - h*H_;
        const float* ww = (g==0) ? w3w : (g==1) ? w4w : w5w;
        const float* wu = (g==0) ? w3u : (g==1) ? w4u : w5u;
        g_weff[i] = ww[h*(2*H_) + k] + ww[h*(2*H_) + H_ + k];
        g_ucat[i] = wu[rem];
    }
    if (i < 3*H_) {
        int g = i / H_, h = i - g*H_;
        const float* bw = (g==0) ? b3w : (g==1) ? b4w : b5w;
        const float* bu = (g==0) ? b3u : (g==1) ? b4u : b5u;
        g_bias[i] = bw[h] + bu[h];
    }
}

__global__ void k_copy_in(const float* __restrict__ src) {
    int n4 = (RN_*H_)/4;
    for (int i = blockIdx.x*blockDim.x + threadIdx.x; i < n4; i += gridDim.x*blockDim.x)
        ((float4*)g_hid0)[i] = ((const float4*)src)[i];
}

// ================= av =================
__global__ void k_av(const float* __restrict__ hid) {
    __shared__ float srow[C_];
    int r = blockIdx.y;
    if (threadIdx.x < C_) srow[threadIdx.x] = g_row[r*C_ + threadIdx.x];
    __syncthreads();
    int h = blockIdx.x*blockDim.x + threadIdx.x;
    const float* hb = hid  + (size_t)r*NODE_*H_;
    float*       ab = g_av + (size_t)r*NODE_*H_;
    float s01 = hb[h] + hb[H_ + h];
    float acc = 0.f;
    #pragma unroll 3
    for (int c = 0; c < C_; ++c) {
        float rc = srow[c];
        acc = fmaf(rc, hb[(2+c)*H_ + h], acc);
        ab[(2+c)*H_ + h] = rc * s01;
    }
    ab[h]      = acc;
    ab[H_ + h] = acc;
}

// ================= tf32 mma.sync dual-GEMM =================
// Tile 128(M) x 128(N), BK=32, 256 threads, 8 warps: warp tile 64x32.
#define ACT_SIG  1
#define ACT_GRU  2
#define ACT_RELU 3

#define BM_  128
#define BN_  128
#define BK_  32
#define STRD 136                         /* smem row stride (floats): conflict-free */
#define BUFSZ (BK_*STRD)                 /* 4352 floats per buffer */
#define SMEM_FLOATS (4*BUFSZ)            /* A0 A1 B0 B1 = 17408 floats = 69632 B */

__device__ __forceinline__ uint32_t f2tf32(float x) {
    uint32_t u;
    asm("cvt.rna.tf32.f32 %0, %1;" : "=r"(u) : "f"(x));
    return u;
}

__device__ __forceinline__ void mma_tf32(float* d, const uint32_t* a, const uint32_t* b) {
    asm volatile(
        "mma.sync.aligned.m16n8k8.row.col.f32.tf32.tf32.f32 "
        "{%0,%1,%2,%3}, {%4,%5,%6,%7}, {%8,%9}, {%0,%1,%2,%3};\n"
        : "+f"(d[0]), "+f"(d[1]), "+f"(d[2]), "+f"(d[3])
        : "r"(a[0]), "r"(a[1]), "r"(a[2]), "r"(a[3]), "r"(b[0]), "r"(b[1]));
}

template<int ACT, bool MUL2>
__global__ void __launch_bounds__(256) k_tmma(
    const float* __restrict__ A1, int lda1, const float* __restrict__ W1, int ldw1,
    const float* __restrict__ A2, int lda2, const float* __restrict__ W2, int ldw2,
    const float* __restrict__ A2m, int ldm,
    const float* __restrict__ bias,
    const float* __restrict__ hidin,   // ACT_GRU: previous hidden f
    const float* __restrict__ zbuf,    // ACT_GRU: zv (stride 1024)
    float* __restrict__ Co, int ldc)
{
    extern __shared__ __align__(16) float sm[];
    float* Asm = sm;                 // [buf][BK][STRD]
    float* Bsm = sm + 2*BUFSZ;

    const int tid  = threadIdx.x;
    const int lane = tid & 31;
    const int wid  = tid >> 5;
    const int wm   = wid >> 2;          // 0..1
    const int wn   = wid & 3;           // 0..3
    const int blockRow = blockIdx.y * BM_;
    const int blockCol = blockIdx.x * BN_;

    // consumer fragment coordinates
    const int kcol = lane & 3;
    const int arow = wm*64 + (lane >> 2);
    const int bcol = wn*32 + (lane >> 2);

    // producer coordinates: thread owns row pm, quads q = pq + 2p (p=0..3)
    const int pm = tid & 127;
    const int pq = tid >> 7;

    float acc[4][4][4];
    #pragma unroll
    for (int i = 0; i < 4; ++i)
        #pragma unroll
        for (int j = 0; j < 4; ++j)
            #pragma unroll
            for (int v = 0; v < 4; ++v) acc[i][j][v] = 0.f;

    const int NCH = 32;     // 2 terms x (512/32)
    float4 ra[4], rb[4];

    // ---- prefetch chunk into registers
    auto prefetch = [&](int chunk) {
        const int term = chunk >> 4;
        const int kk0  = (chunk & 15) * BK_;
        const float* A  = term ? A2 : A1;  const int lda = term ? lda2 : lda1;
        const float* W  = term ? W2 : W1;  const int ldw = term ? ldw2 : ldw1;
        const float4* Arow = (const float4*)(A + (size_t)(blockRow + pm)*lda + kk0);
        const float4* Wrow = (const float4*)(W + (size_t)(blockCol + pm)*ldw + kk0);
        #pragma unroll
        for (int p = 0; p < 4; ++p) {
            int q = pq + 2*p;
            float4 v = Arow[q];
            if (MUL2 && term == 1) {
                const float4* Mrow = (const float4*)(A2m + (size_t)(blockRow + pm)*ldm + kk0);
                float4 mu = Mrow[q];
                v.x *= mu.x; v.y *= mu.y; v.z *= mu.z; v.w *= mu.w;
            }
            ra[p] = v;
            rb[p] = Wrow[q];
        }
    };
    // ---- store prefetched regs to smem buffer (tf32-converted)
    auto store_chunk = [&](int buf) {
        float* Ab = Asm + buf*BUFSZ;
        float* Bb = Bsm + buf*BUFSZ;
        #pragma unroll
        for (int p = 0; p < 4; ++p) {
            int k0 = (pq + 2*p) * 4;
            Ab[(k0+0)*STRD + pm] = __uint_as_float(f2tf32(ra[p].x));
            Ab[(k0+1)*STRD + pm] = __uint_as_float(f2tf32(ra[p].y));
            Ab[(k0+2)*STRD + pm] = __uint_as_float(f2tf32(ra[p].z));
            Ab[(k0+3)*STRD + pm] = __uint_as_float(f2tf32(ra[p].w));
            Bb[(k0+0)*STRD + pm] = __uint_as_float(f2tf32(rb[p].x));
            Bb[(k0+1)*STRD + pm] = __uint_as_float(f2tf32(rb[p].y));
            Bb[(k0+2)*STRD + pm] = __uint_as_float(f2tf32(rb[p].z));
            Bb[(k0+3)*STRD + pm] = __uint_as_float(f2tf32(rb[p].w));
        }
    };
    // ---- consume one buffer (BK=32 -> 4 k8 steps)
    auto compute = [&](int buf) {
        const float* Ab = Asm + buf*BUFSZ;
        const float* Bb = Bsm + buf*BUFSZ;
        #pragma unroll
        for (int s = 0; s < 4; ++s) {
            const float* Ak = Ab + (s*8 + kcol)*STRD;
            const float* Bk = Bb + (s*8 + kcol)*STRD;
            uint32_t af[4][4], bf[4][2];
            #pragma unroll
            for (int i = 0; i < 4; ++i) {
                int r0 = arow + i*16;
                af[i][0] = __float_as_uint(Ak[r0]);
                af[i][1] = __float_as_uint(Ak[r0 + 8]);
                af[i][2] = __float_as_uint(Ak[4*STRD + r0]);
                af[i][3] = __float_as_uint(Ak[4*STRD + r0 + 8]);
            }
            #pragma unroll
            for (int j = 0; j < 4; ++j) {
                int c0 = bcol + j*8;
                bf[j][0] = __float_as_uint(Bk[c0]);
                bf[j][1] = __float_as_uint(Bk[4*STRD + c0]);
            }
            #pragma unroll
            for (int i = 0; i < 4; ++i)
                #pragma unroll
                for (int j = 0; j < 4; ++j)
                    mma_tf32(acc[i][j], af[i], bf[j]);
        }
    };

    prefetch(0);
    store_chunk(0);
    __syncthreads();

    for (int c = 0; c < NCH; ++c) {
        if (c + 1 < NCH) prefetch(c + 1);
        compute(c & 1);
        if (c + 1 < NCH) store_chunk((c + 1) & 1);
        __syncthreads();
    }

    // ---- epilogue
    #pragma unroll
    for (int i = 0; i < 4; ++i) {
        const int r0 = blockRow + wm*64 + i*16 + (lane >> 2);
        #pragma unroll
        for (int j = 0; j < 4; ++j) {
            const int gc = blockCol + wn*32 + j*8 + (lane & 3)*2;
            float2 bs = *(const float2*)&bias[gc];
            float v0 = acc[i][j][0] + bs.x;
            float v1 = acc[i][j][1] + bs.y;
            float v2 = acc[i][j][2] + bs.x;
            float v3 = acc[i][j][3] + bs.y;
            float2 o01, o23;
            if (ACT == ACT_SIG) {
                o01.x = 1.f/(1.f+__expf(-v0)); o01.y = 1.f/(1.f+__expf(-v1));
                o23.x = 1.f/(1.f+__expf(-v2)); o23.y = 1.f/(1.f+__expf(-v3));
            } else if (ACT == ACT_RELU) {
                o01.x = fmaxf(v0,0.f); o01.y = fmaxf(v1,0.f);
                o23.x = fmaxf(v2,0.f); o23.y = fmaxf(v3,0.f);
            } else {   // GRU: h' = (1-z)*f + z*tanh(v)
                float2 z0 = *(const float2*)&zbuf [(size_t)r0*1024 + gc];
                float2 f0 = *(const float2*)&hidin[(size_t)r0*512  + gc];
                float2 z1 = *(const float2*)&zbuf [(size_t)(r0+8)*1024 + gc];
                float2 f1 = *(const float2*)&hidin[(size_t)(r0+8)*512  + gc];
                o01.x = (1.f-z0.x)*f0.x + z0.x*tanhf(v0);
                o01.y = (1.f-z0.y)*f0.y + z0.y*tanhf(v1);
                o23.x = (1.f-z1.x)*f1.x + z1.x*tanhf(v2);
                o23.y = (1.f-z1.y)*f1.y + z1.y*tanhf(v3);
            }
            *(float2*)&Co[(size_t)r0*ldc + gc]     = o01;
            *(float2*)&Co[(size_t)(r0+8)*ldc + gc] = o23;
        }
    }
}

// ================= FFMA split-K GEMM (final skinny GEMM, exact fp32) =========
__global__ void __launch_bounds__(256) k_gemm_ffma(
    const float* __restrict__ A1, int lda1, const float* __restrict__ W1, int ldw1,
    float* __restrict__ Co, int ldc, int M, int N, int K)
{
    __shared__ __align__(16) float As[16][128];
    __shared__ __align__(16) float Ws[16][64];
    const int tx = threadIdx.x & 15;
    const int ty = threadIdx.x >> 4;
    const int blockRow = blockIdx.y * 128;
    const int blockCol = blockIdx.x * 64;
    int kbeg = blockIdx.z * KSLICE_;
    int kend = kbeg + KSLICE_;
    float acc[8][4];
    #pragma unroll
    for (int i = 0; i < 8; ++i)
        #pragma unroll
        for (int j = 0; j < 4; ++j) acc[i][j] = 0.f;
    for (int k0 = kbeg; k0 < kend; k0 += 16) {
        #pragma unroll
        for (int t = 0; t < 2; ++t) {
            int l = threadIdx.x + t*256;
            int m = l >> 2, kv = (l & 3) << 2;
            float4 v = *(const float4*)&A1[(size_t)(blockRow + m)*lda1 + k0 + kv];
            As[kv+0][m] = v.x; As[kv+1][m] = v.y; As[kv+2][m] = v.z; As[kv+3][m] = v.w;
        }
        {
            int n = threadIdx.x >> 2, kv = (threadIdx.x & 3) << 2;
            int gn = blockCol + n;
            float4 v = make_float4(0.f,0.f,0.f,0.f);
            if (gn < N) v = *(const float4*)&W1[(size_t)gn*ldw1 + k0 + kv];
            Ws[kv+0][n] = v.x; Ws[kv+1][n] = v.y; Ws[kv+2][n] = v.z; Ws[kv+3][n] = v.w;
        }
        __syncthreads();
        #pragma unroll
        for (int kk = 0; kk < 16; ++kk) {
            float a[8], bv[4];
            *(float4*)&a[0] = *(const float4*)&As[kk][ty*8];
            *(float4*)&a[4] = *(const float4*)&As[kk][ty*8+4];
            *(float4*)&bv[0] = *(const float4*)&Ws[kk][tx*4];
            #pragma unroll
            for (int i = 0; i < 8; ++i)
                #pragma unroll
                for (int j = 0; j < 4; ++j)
                    acc[i][j] = fmaf(a[i], bv[j], acc[i][j]);
        }
        __syncthreads();
    }
    size_t outBase = (size_t)blockIdx.z * (size_t)M * ldc;
    #pragma unroll
    for (int i = 0; i < 8; ++i) {
        int gmm = blockRow + ty*8 + i;
        #pragma unroll
        for (int j = 0; j < 4; ++j) {
            int gn = blockCol + tx*4 + j;
            if (gn < N) Co[outBase + (size_t)gmm*ldc + gn] = acc[i][j];
        }
    }
}

__global__ void k_reduce(const float* __restrict__ bc, float* __restrict__ out) {
    int i = blockIdx.x*blockDim.x + threadIdx.x;
    if (i >= R_*C_) return;
    float s = bc[i % C_];
    #pragma unroll
    for (int z = 0; z < SPLITS_; ++z) s += g_part[(size_t)z*R_*C_ + i];
    out[i] = s;
}

// ================= launch =================
extern "C" void kernel_launch(void* const* d_in, const int* in_sizes, int n_in,
                              void* d_out, int out_size) {
    const int*   sop    = (const int*)  d_in[1];
    const float* input  = (const float*)d_in[2];
    const float* matrix = (const float*)d_in[4];
    const float* w3w = (const float*)d_in[5];  const float* b3w = (const float*)d_in[6];
    const float* w3u = (const float*)d_in[7];  const float* b3u = (const float*)d_in[8];
    const float* w4w = (const float*)d_in[9];  const float* b4w = (const float*)d_in[10];
    const float* w4u = (const float*)d_in[11]; const float* b4u = (const float*)d_in[12];
    const float* w5w = (const float*)d_in[13]; const float* b5w = (const float*)d_in[14];
    const float* w5u = (const float*)d_in[15]; const float* b5u = (const float*)d_in[16];
    const float* wo  = (const float*)d_in[17]; const float* bo  = (const float*)d_in[18];
    const float* wc  = (const float*)d_in[19]; const float* bc  = (const float*)d_in[20];
    float* out = (float*)d_out;

    float *p_h0, *p_h1, *p_av, *p_zr, *p_out, *p_weff, *p_ucat, *p_bias, *p_part;
    cudaGetSymbolAddress((void**)&p_h0,   g_hid0);
    cudaGetSymbolAddress((void**)&p_h1,   g_hid1);
    cudaGetSymbolAddress((void**)&p_av,   g_av);
    cudaGetSymbolAddress((void**)&p_zr,   g_zr);
    cudaGetSymbolAddress((void**)&p_out,  g_out);
    cudaGetSymbolAddress((void**)&p_weff, g_weff);
    cudaGetSymbolAddress((void**)&p_ucat, g_ucat);
    cudaGetSymbolAddress((void**)&p_bias, g_bias);
    cudaGetSymbolAddress((void**)&p_part, g_part);

    const int smemBytes = SMEM_FLOATS * 4;  // 69632
    cudaFuncSetAttribute(k_tmma<ACT_SIG,false>,  cudaFuncAttributeMaxDynamicSharedMemorySize, smemBytes);
    cudaFuncSetAttribute(k_tmma<ACT_GRU,true>,   cudaFuncAttributeMaxDynamicSharedMemorySize, smemBytes);
    cudaFuncSetAttribute(k_tmma<ACT_RELU,false>, cudaFuncAttributeMaxDynamicSharedMemorySize, smemBytes);

    k_prep_row<<<(R_*C_ + 255)/256, 256>>>(sop, matrix);
    k_prep_w<<<(3*H_*H_ + 255)/256, 256>>>(w3w, w3u, b3w, b3u,
                                           w4w, w4u, b4w, b4u,
                                           w5w, w5u, b5w, b5u);
    k_copy_in<<<4096, 256>>>(input);

    dim3 gGate(1024/BN_, RN_/BM_);   // 8 x 848
    dim3 gHv  (512/BN_,  RN_/BM_);   // 4 x 848

    float* hin  = p_h0;
    float* hout = p_h1;
    for (int t = 0; t < T_; ++t) {
        k_av<<<dim3(2, R_), 256>>>(hin);
        // [zv|rv] = sigmoid(av@[W3e;W4e].T + fh@[w3u;w4u].T + bias)
        k_tmma<ACT_SIG,false><<<gGate, 256, smemBytes>>>(
            p_av, H_, p_weff, H_,
            hin,  H_, p_ucat, H_,
            nullptr, 0, p_bias, nullptr, nullptr, p_zr, 1024);
        // hidden' = (1-z)*f + z*tanh(av@W5e.T + (rv*fh)@w5u.T + b5)
        k_tmma<ACT_GRU,true><<<gHv, 256, smemBytes>>>(
            p_av, H_, p_weff + 2*H_*H_, H_,
            hin,  H_, p_ucat + 2*H_*H_, H_,
            p_zr + H_, 1024, p_bias + 2*H_, hin, p_zr, hout, H_);
        float* tmp = hin; hin = hout; hout = tmp;
    }

    // out = relu(fh@wo[:, :H].T + input@wo[:, H:].T + bo)
    k_tmma<ACT_RELU,false><<<gHv, 256, smemBytes>>>(
        hin, H_, wo, 2*H_,
        input, H_, wo + H_, 2*H_,
        nullptr, 0, bo, nullptr, nullptr, p_out, OUT_);

    // rel_dists = out.reshape(R, 27136) @ wc.T + bc   (split-K FFMA, exact)
    k_gemm_ffma<<<dim3(1, R_/128, SPLITS_), 256>>>(
        p_out, K2_, wc, K2_, p_part, C_, R_, C_, K2_);
    k_reduce<<<(R_*C_ + 255)/256, 256>>>(bc, out);
}

// round 4
// speedup vs baseline: 3.6357x; 2.0606x over previous
#include <cuda_runtime.h>
#include <math.h>
#include <stdint.h>

#define R_    2048
#define NODE_ 53
#define H_    512
#define C_    51
#define NOBJ_ 151
#define OUT_  512
#define T_    3
#define RN_   (R_*NODE_)      /* 108544 */
#define K2_   (NODE_*OUT_)    /* 27136  */
#define SPLITS_ 32
#define KSLICE_ (K2_/SPLITS_) /* 848 */

// ================= tf32 helpers =================
__device__ __forceinline__ uint32_t f2tf32(float x) {
    uint32_t u;
    asm("cvt.rna.tf32.f32 %0, %1;" : "=r"(u) : "f"(x));
    return u;
}
__device__ __forceinline__ float rtf(float x) { return __uint_as_float(f2tf32(x)); }

__device__ __forceinline__ void mma_tf32(float* d, const uint32_t* a, const uint32_t* b) {
    asm volatile(
        "mma.sync.aligned.m16n8k8.row.col.f32.tf32.tf32.f32 "
        "{%0,%1,%2,%3}, {%4,%5,%6,%7}, {%8,%9}, {%0,%1,%2,%3};\n"
        : "+f"(d[0]), "+f"(d[1]), "+f"(d[2]), "+f"(d[3])
        : "r"(a[0]), "r"(a[1]), "r"(a[2]), "r"(a[3]), "r"(b[0]), "r"(b[1]));
}
__device__ __forceinline__ uint32_t smem_u32(const void* p) {
    uint32_t a;
    asm("{ .reg .u64 t; cvta.to.shared.u64 t, %1; cvt.u32.u64 %0, t; }" : "=r"(a) : "l"(p));
    return a;
}
__device__ __forceinline__ void cp_async16(uint32_t s, const void* g) {
    asm volatile("cp.async.cg.shared.global [%0], [%1], 16;" :: "r"(s), "l"(g));
}
#define CP_COMMIT() asm volatile("cp.async.commit_group;" ::: "memory")
#define CP_WAIT(n)  asm volatile("cp.async.wait_group %0;" :: "n"(n) : "memory")

// ================= scratch =================
__device__ float g_hid0 [RN_*H_];
__device__ float g_hid1 [RN_*H_];
__device__ float g_inp  [RN_*H_];     // tf32-rounded copy of input
__device__ float g_av   [RN_*H_];
__device__ float g_z    [RN_*H_];     // zv
__device__ float g_rf   [RN_*H_];     // tf32(rv * f)
__device__ float g_out  [RN_*OUT_];
__device__ float g_weff [3*H_*H_];
__device__ float g_ucat [3*H_*H_];
__device__ float g_wor  [2*H_*H_];    // rounded wo, split halves stacked
__device__ float g_bias [3*H_];
__device__ float g_row  [R_*C_];
__device__ float g_part [SPLITS_*R_*C_];

// ================= prep =================
__global__ void k_prep_row(const int* __restrict__ sop, const float* __restrict__ matrix) {
    int i = blockIdx.x*blockDim.x + threadIdx.x;
    if (i >= R_*C_) return;
    int r = i / C_, c = i - r*C_;
    g_row[i] = matrix[((size_t)sop[2*r]*NOBJ_ + sop[2*r+1])*C_ + c];
}

__global__ void k_prep_w(const float* w3w, const float* w3u, const float* b3w, const float* b3u,
                         const float* w4w, const float* w4u, const float* b4w, const float* b4u,
                         const float* w5w, const float* w5u, const float* b5w, const float* b5u) {
    int i = blockIdx.x*blockDim.x + threadIdx.x;
    if (i < 3*H_*H_) {
        int g = i / (H_*H_);
        int rem = i - g*(H_*H_);
        int h = rem / H_, k = rem - h*H_;
        const float* ww = (g==0) ? w3w : (g==1) ? w4w : w5w;
        const float* wu = (g==0) ? w3u : (g==1) ? w4u : w5u;
        g_weff[i] = rtf(ww[h*(2*H_) + k] + ww[h*(2*H_) + H_ + k]);
        g_ucat[i] = rtf(wu[rem]);
    }
    if (i < 3*H_) {
        int g = i / H_, h = i - g*H_;
        const float* bw = (g==0) ? b3w : (g==1) ? b4w : b5w;
        const float* bu = (g==0) ? b3u : (g==1) ? b4u : b5u;
        g_bias[i] = bw[h] + bu[h];
    }
}

__global__ void k_prep_wo(const float* __restrict__ wo) {
    int i = blockIdx.x*blockDim.x + threadIdx.x;     // over 512*1024
    if (i >= H_*2*H_) return;
    int row = i >> 10, col = i & 1023;
    int dst = (col < H_) ? row*H_ + col : (row + H_)*H_ + (col - H_);
    g_wor[dst] = rtf(wo[i]);
}

__global__ void k_copy_in(const float* __restrict__ src) {
    int n = RN_*H_;
    for (int i = blockIdx.x*blockDim.x + threadIdx.x; i < n; i += gridDim.x*blockDim.x) {
        float v = rtf(src[i]);
        g_hid0[i] = v;
        g_inp [i] = v;
    }
}

// ================= av (writes tf32-rounded) =================
__global__ void k_av(const float* __restrict__ hid) {
    __shared__ float srow[C_];
    int r = blockIdx.y;
    if (threadIdx.x < C_) srow[threadIdx.x] = g_row[r*C_ + threadIdx.x];
    __syncthreads();
    int h = blockIdx.x*blockDim.x + threadIdx.x;
    const float* hb = hid  + (size_t)r*NODE_*H_;
    float*       ab = g_av + (size_t)r*NODE_*H_;
    float s01 = hb[h] + hb[H_ + h];
    float acc = 0.f;
    #pragma unroll 3
    for (int c = 0; c < C_; ++c) {
        float rc = srow[c];
        acc = fmaf(rc, hb[(2+c)*H_ + h], acc);
        ab[(2+c)*H_ + h] = rtf(rc * s01);
    }
    float accr = rtf(acc);
    ab[h]      = accr;
    ab[H_ + h] = accr;
}

// ================= tf32 mma GEMM: CTA 128x128, 4 warps (2x2), warp 64x64 ====
// C = EPI( A1 @ W1^T + A2 @ W2^T + bias ), K = 512 per term, all strides 512.
#define ACT_GATE 1
#define ACT_GRU  2
#define ACT_RELU 3

#define STG_AFL   (128*36)                 /* A floats per stage  */
#define STG_FL    (2*STG_AFL)              /* stage floats (A+B)  */
#define STG_BYTES (STG_FL*4)               /* 36864               */
#define SMEM_BYTES (3*STG_BYTES)           /* 110592              */

template<int ACT>
__global__ void __launch_bounds__(128, 2) k_tmma(
    const float* __restrict__ A1, const float* __restrict__ W1,
    const float* __restrict__ A2, const float* __restrict__ W2,
    const float* __restrict__ bias,
    const float* __restrict__ hidin,   // GATE: f for rf product; GRU: previous hidden
    const float* __restrict__ zbuf,    // GRU: zv (stride 512)
    float* __restrict__ Co)            // GATE: g_z base (g_rf implicit); else output
{
    extern __shared__ __align__(16) float sm[];
    const uint32_t smem_base = smem_u32(sm);
    const int tid  = threadIdx.x;
    const int lane = tid & 31;
    const int wid  = tid >> 5;
    const int wm   = wid >> 1, wn = wid & 1;
    const int blockRow = blockIdx.y * 128;
    const int blockCol = blockIdx.x * 128;

    float acc[4][8][4];
    #pragma unroll
    for (int i = 0; i < 4; ++i)
        #pragma unroll
        for (int j = 0; j < 8; ++j)
            #pragma unroll
            for (int v = 0; v < 4; ++v) acc[i][j][v] = 0.f;

    const int mrow = tid >> 3;        // producer row base (0..15)
    const int qk   = tid & 7;         // producer k-quad

    auto load_chunk = [&](int c, int stage) {
        const int term = c >> 4;
        const int kk0  = (c & 15) * 32;
        const float* A = term ? A2 : A1;
        const float* W = term ? W2 : W1;
        const float* Ag = A + (size_t)(blockRow + mrow)*512 + kk0 + qk*4;
        const float* Wg = W + (size_t)(blockCol + mrow)*512 + kk0 + qk*4;
        uint32_t sa = smem_base + stage*STG_BYTES + mrow*144 + qk*16;
        uint32_t sb = sa + STG_AFL*4;
        #pragma unroll
        for (int p = 0; p < 8; ++p) {
            cp_async16(sa + p*16*144, Ag + (size_t)p*16*512);
            cp_async16(sb + p*16*144, Wg + (size_t)p*16*512);
        }
    };

    auto compute = [&](int stage) {
        const float* Sa = sm + stage*STG_FL;
        const float* Sb = Sa + STG_AFL;
        #pragma unroll
        for (int s = 0; s < 4; ++s) {
            const int kpos = s*8 + (lane & 3);
            uint32_t af[4][4], bf[8][2];
            #pragma unroll
            for (int i = 0; i < 4; ++i) {
                const int r0 = wm*64 + i*16 + (lane >> 2);
                af[i][0] = __float_as_uint(Sa[r0*36 + kpos]);
                af[i][1] = __float_as_uint(Sa[(r0+8)*36 + kpos]);
                af[i][2] = __float_as_uint(Sa[r0*36 + kpos + 4]);
                af[i][3] = __float_as_uint(Sa[(r0+8)*36 + kpos + 4]);
            }
            #pragma unroll
            for (int j = 0; j < 8; ++j) {
                const int c0 = wn*64 + j*8 + (lane >> 2);
                bf[j][0] = __float_as_uint(Sb[c0*36 + kpos]);
                bf[j][1] = __float_as_uint(Sb[c0*36 + kpos + 4]);
            }
            #pragma unroll
            for (int i = 0; i < 4; ++i)
                #pragma unroll
                for (int j = 0; j < 8; ++j)
                    mma_tf32(acc[i][j], af[i], bf[j]);
        }
    };

    const int NCH = 32;
    load_chunk(0, 0); CP_COMMIT();
    load_chunk(1, 1); CP_COMMIT();

    int stage_n = 2;   // stage for chunk c+2
    for (int c = 0; c < NCH; ++c) {
        CP_WAIT(1);
        __syncthreads();
        if (c + 2 < NCH) load_chunk(c + 2, stage_n);
        CP_COMMIT();
        int stage_c = stage_n + 1; if (stage_c >= 3) stage_c -= 3;   // == c%3
        compute(stage_c);
        stage_n = stage_c;   // buffer just consumed becomes next load target (after sync)
    }
    CP_WAIT(0);

    // ---- epilogue
    #pragma unroll
    for (int i = 0; i < 4; ++i) {
        const int r0 = blockRow + wm*64 + i*16 + (lane >> 2);
        #pragma unroll
        for (int j = 0; j < 8; ++j) {
            const int gc = blockCol + wn*64 + j*8 + (lane & 3)*2;
            float2 bs = *(const float2*)&bias[gc];
            float v0 = acc[i][j][0] + bs.x;
            float v1 = acc[i][j][1] + bs.y;
            float v2 = acc[i][j][2] + bs.x;
            float v3 = acc[i][j][3] + bs.y;
            if (ACT == ACT_GATE) {
                float s0 = 1.f/(1.f+__expf(-v0)), s1 = 1.f/(1.f+__expf(-v1));
                float s2 = 1.f/(1.f+__expf(-v2)), s3 = 1.f/(1.f+__expf(-v3));
                if (gc < 512) {   // zv half (uniform per CTA)
                    *(float2*)&Co[(size_t)r0*512 + gc]     = make_float2(s0, s1);
                    *(float2*)&Co[(size_t)(r0+8)*512 + gc] = make_float2(s2, s3);
                } else {          // rv half -> rf = tf32(rv * f)
                    const int hc = gc - 512;
                    float2 f0 = *(const float2*)&hidin[(size_t)r0*512 + hc];
                    float2 f1 = *(const float2*)&hidin[(size_t)(r0+8)*512 + hc];
                    *(float2*)&g_rf[(size_t)r0*512 + hc]     = make_float2(rtf(s0*f0.x), rtf(s1*f0.y));
                    *(float2*)&g_rf[(size_t)(r0+8)*512 + hc] = make_float2(rtf(s2*f1.x), rtf(s3*f1.y));
                }
            } else if (ACT == ACT_RELU) {
                *(float2*)&Co[(size_t)r0*512 + gc]     = make_float2(fmaxf(v0,0.f), fmaxf(v1,0.f));
                *(float2*)&Co[(size_t)(r0+8)*512 + gc] = make_float2(fmaxf(v2,0.f), fmaxf(v3,0.f));
            } else {  // GRU: h' = tf32((1-z)*f + z*tanh(v))
                float2 z0 = *(const float2*)&zbuf [(size_t)r0*512 + gc];
                float2 f0 = *(const float2*)&hidin[(size_t)r0*512 + gc];
                float2 z1 = *(const float2*)&zbuf [(size_t)(r0+8)*512 + gc];
                float2 f1 = *(const float2*)&hidin[(size_t)(r0+8)*512 + gc];
                float o0 = (1.f-z0.x)*f0.x + z0.x*tanhf(v0);
                float o1 = (1.f-z0.y)*f0.y + z0.y*tanhf(v1);
                float o2 = (1.f-z1.x)*f1.x + z1.x*tanhf(v2);
                float o3 = (1.f-z1.y)*f1.y + z1.y*tanhf(v3);
                *(float2*)&Co[(size_t)r0*512 + gc]     = make_float2(rtf(o0), rtf(o1));
                *(float2*)&Co[(size_t)(r0+8)*512 + gc] = make_float2(rtf(o2), rtf(o3));
            }
        }
    }
}

// ================= FFMA split-K GEMM (final skinny GEMM, exact fp32) =========
__global__ void __launch_bounds__(256) k_gemm_ffma(
    const float* __restrict__ A1, int lda1, const float* __restrict__ W1, int ldw1,
    float* __restrict__ Co, int ldc, int M, int N, int K)
{
    __shared__ __align__(16) float As[16][128];
    __shared__ __align__(16) float Ws[16][64];
    const int tx = threadIdx.x & 15;
    const int ty = threadIdx.x >> 4;
    const int blockRow = blockIdx.y * 128;
    const int blockCol = blockIdx.x * 64;
    int kbeg = blockIdx.z * KSLICE_;
    int kend = kbeg + KSLICE_;
    float acc[8][4];
    #pragma unroll
    for (int i = 0; i < 8; ++i)
        #pragma unroll
        for (int j = 0; j < 4; ++j) acc[i][j] = 0.f;
    for (int k0 = kbeg; k0 < kend; k0 += 16) {
        #pragma unroll
        for (int t = 0; t < 2; ++t) {
            int l = threadIdx.x + t*256;
            int m = l >> 2, kv = (l & 3) << 2;
            float4 v = *(const float4*)&A1[(size_t)(blockRow + m)*lda1 + k0 + kv];
            As[kv+0][m] = v.x; As[kv+1][m] = v.y; As[kv+2][m] = v.z; As[kv+3][m] = v.w;
        }
        {
            int n = threadIdx.x >> 2, kv = (threadIdx.x & 3) << 2;
            int gn = blockCol + n;
            float4 v = make_float4(0.f,0.f,0.f,0.f);
            if (gn < N) v = *(const float4*)&W1[(size_t)gn*ldw1 + k0 + kv];
            Ws[kv+0][n] = v.x; Ws[kv+1][n] = v.y; Ws[kv+2][n] = v.z; Ws[kv+3][n] = v.w;
        }
        __syncthreads();
        #pragma unroll
        for (int kk = 0; kk < 16; ++kk) {
            float a[8], bv[4];
            *(float4*)&a[0] = *(const float4*)&As[kk][ty*8];
            *(float4*)&a[4] = *(const float4*)&As[kk][ty*8+4];
            *(float4*)&bv[0] = *(const float4*)&Ws[kk][tx*4];
            #pragma unroll
            for (int i = 0; i < 8; ++i)
                #pragma unroll
                for (int j = 0; j < 4; ++j)
                    acc[i][j] = fmaf(a[i], bv[j], acc[i][j]);
        }
        __syncthreads();
    }
    size_t outBase = (size_t)blockIdx.z * (size_t)M * ldc;
    #pragma unroll
    for (int i = 0; i < 8; ++i) {
        int gmm = blockRow + ty*8 + i;
        #pragma unroll
        for (int j = 0; j < 4; ++j) {
            int gn = blockCol + tx*4 + j;
            if (gn < N) Co[outBase + (size_t)gmm*ldc + gn] = acc[i][j];
        }
    }
}

__global__ void k_reduce(const float* __restrict__ bc, float* __restrict__ out) {
    int i = blockIdx.x*blockDim.x + threadIdx.x;
    if (i >= R_*C_) return;
    float s = bc[i % C_];
    #pragma unroll
    for (int z = 0; z < SPLITS_; ++z) s += g_part[(size_t)z*R_*C_ + i];
    out[i] = s;
}

// ================= launch =================
extern "C" void kernel_launch(void* const* d_in, const int* in_sizes, int n_in,
                              void* d_out, int out_size) {
    const int*   sop    = (const int*)  d_in[1];
    const float* input  = (const float*)d_in[2];
    const float* matrix = (const float*)d_in[4];
    const float* w3w = (const float*)d_in[5];  const float* b3w = (const float*)d_in[6];
    const float* w3u = (const float*)d_in[7];  const float* b3u = (const float*)d_in[8];
    const float* w4w = (const float*)d_in[9];  const float* b4w = (const float*)d_in[10];
    const float* w4u = (const float*)d_in[11]; const float* b4u = (const float*)d_in[12];
    const float* w5w = (const float*)d_in[13]; const float* b5w = (const float*)d_in[14];
    const float* w5u = (const float*)d_in[15]; const float* b5u = (const float*)d_in[16];
    const float* wo  = (const float*)d_in[17]; const float* bo  = (const float*)d_in[18];
    const float* wc  = (const float*)d_in[19]; const float* bc  = (const float*)d_in[20];
    float* out = (float*)d_out;

    float *p_h0, *p_h1, *p_inp, *p_av, *p_z, *p_rf, *p_out, *p_weff, *p_ucat, *p_wor, *p_bias;
    cudaGetSymbolAddress((void**)&p_h0,   g_hid0);
    cudaGetSymbolAddress((void**)&p_h1,   g_hid1);
    cudaGetSymbolAddress((void**)&p_inp,  g_inp);
    cudaGetSymbolAddress((void**)&p_av,   g_av);
    cudaGetSymbolAddress((void**)&p_z,    g_z);
    cudaGetSymbolAddress((void**)&p_rf,   g_rf);
    cudaGetSymbolAddress((void**)&p_out,  g_out);
    cudaGetSymbolAddress((void**)&p_weff, g_weff);
    cudaGetSymbolAddress((void**)&p_ucat, g_ucat);
    cudaGetSymbolAddress((void**)&p_wor,  g_wor);
    cudaGetSymbolAddress((void**)&p_bias, g_bias);
    float* p_part;
    cudaGetSymbolAddress((void**)&p_part, g_part);

    cudaFuncSetAttribute(k_tmma<ACT_GATE>, cudaFuncAttributeMaxDynamicSharedMemorySize, SMEM_BYTES);
    cudaFuncSetAttribute(k_tmma<ACT_GRU>,  cudaFuncAttributeMaxDynamicSharedMemorySize, SMEM_BYTES);
    cudaFuncSetAttribute(k_tmma<ACT_RELU>, cudaFuncAttributeMaxDynamicSharedMemorySize, SMEM_BYTES);

    k_prep_row<<<(R_*C_ + 255)/256, 256>>>(sop, matrix);
    k_prep_w<<<(3*H_*H_ + 255)/256, 256>>>(w3w, w3u, b3w, b3u,
                                           w4w, w4u, b4w, b4u,
                                           w5w, w5u, b5w, b5u);
    k_prep_wo<<<(2*H_*H_ + 255)/256, 256>>>(wo);
    k_copy_in<<<2048, 256>>>(input);

    dim3 gGate(1024/128, RN_/128);   // 8 x 848
    dim3 gHv  (512/128,  RN_/128);   // 4 x 848

    float* hin  = p_h0;
    float* hout = p_h1;
    for (int t = 0; t < T_; ++t) {
        k_av<<<dim3(2, R_), 256>>>(hin);
        // zv (cols 0-511) and rf = tf32(rv*f) (cols 512-1023)
        k_tmma<ACT_GATE><<<gGate, 128, SMEM_BYTES>>>(
            p_av, p_weff, hin, p_ucat, p_bias, hin, nullptr, p_z);
        // hidden' = tf32((1-z)*f + z*tanh(av@W5e.T + rf@w5u.T + b5))
        k_tmma<ACT_GRU><<<gHv, 128, SMEM_BYTES>>>(
            p_av, p_weff + 2*H_*H_, p_rf, p_ucat + 2*H_*H_, p_bias + 2*H_,
            hin, p_z, hout);
        float* tmp = hin; hin = hout; hout = tmp;
    }

    // out = relu(fh@wo[:, :H].T + input@wo[:, H:].T + bo)
    k_tmma<ACT_RELU><<<gHv, 128, SMEM_BYTES>>>(
        hin, p_wor, p_inp, p_wor + H_*H_, bo, nullptr, nullptr, p_out);

    // rel_dists = out.reshape(R, 27136) @ wc.T + bc   (split-K FFMA, exact)
    k_gemm_ffma<<<dim3(1, R_/128, SPLITS_), 256>>>(
        p_out, K2_, wc, K2_, p_part, C_, R_, C_, K2_);
    k_reduce<<<(R_*C_ + 255)/256, 256>>>(bc, out);
}

// round 5
// speedup vs baseline: 3.6381x; 1.0007x over previous
#include <cuda_runtime.h>
#include <math.h>
#include <stdint.h>

#define R_    2048
#define NODE_ 53
#define H_    512
#define C_    51
#define NOBJ_ 151
#define OUT_  512
#define T_    3
#define RN_   (R_*NODE_)      /* 108544 */
#define K2_   (NODE_*OUT_)    /* 27136  */
#define SPLITS_ 32
#define KSLICE_ (K2_/SPLITS_) /* 848 */

// ================= tf32 / mma helpers =================
__device__ __forceinline__ uint32_t f2tf32(float x) {
    uint32_t u;
    asm("cvt.rna.tf32.f32 %0, %1;" : "=r"(u) : "f"(x));
    return u;
}
__device__ __forceinline__ float rtf(float x) { return __uint_as_float(f2tf32(x)); }

__device__ __forceinline__ void mma_tf32(float* d, const uint32_t* a, const uint32_t* b) {
    asm volatile(
        "mma.sync.aligned.m16n8k8.row.col.f32.tf32.tf32.f32 "
        "{%0,%1,%2,%3}, {%4,%5,%6,%7}, {%8,%9}, {%0,%1,%2,%3};\n"
        : "+f"(d[0]), "+f"(d[1]), "+f"(d[2]), "+f"(d[3])
        : "r"(a[0]), "r"(a[1]), "r"(a[2]), "r"(a[3]), "r"(b[0]), "r"(b[1]));
}
__device__ __forceinline__ void ldsm4(uint32_t* r, uint32_t addr) {
    asm volatile("ldmatrix.sync.aligned.m8n8.x4.shared.b16 {%0,%1,%2,%3}, [%4];"
        : "=r"(r[0]), "=r"(r[1]), "=r"(r[2]), "=r"(r[3]) : "r"(addr));
}
__device__ __forceinline__ uint32_t smem_u32(const void* p) {
    uint32_t a;
    asm("{ .reg .u64 t; cvta.to.shared.u64 t, %1; cvt.u32.u64 %0, t; }" : "=r"(a) : "l"(p));
    return a;
}
__device__ __forceinline__ void cp_async16(uint32_t s, const void* g) {
    asm volatile("cp.async.cg.shared.global [%0], [%1], 16;" :: "r"(s), "l"(g));
}
#define CP_COMMIT() asm volatile("cp.async.commit_group;" ::: "memory")
#define CP_WAIT(n)  asm volatile("cp.async.wait_group %0;" :: "n"(n) : "memory")

// ================= scratch =================
__device__ float g_hid0 [RN_*H_];
__device__ float g_hid1 [RN_*H_];
__device__ float g_inp  [RN_*H_];     // tf32-rounded input == initial hidden
__device__ float g_av   [RN_*H_];
__device__ float g_z    [RN_*H_];     // zv
__device__ float g_rf   [RN_*H_];     // tf32(rv * f)
__device__ float g_out  [RN_*OUT_];
__device__ float g_weff [3*H_*H_];
__device__ float g_ucat [3*H_*H_];
__device__ float g_wor  [2*H_*H_];    // rounded wo, halves stacked
__device__ float g_bias [3*H_];
__device__ float g_row  [R_*C_];
__device__ float g_part [SPLITS_*R_*C_];

// ================= combined prep =================
#define PREP_W_  (3*H_*H_)            /* 786432 */
#define PREP_WO_ (2*H_*H_)            /* 524288 */
#define PREP_ROW_ (R_*C_)             /* 104448 */
#define PREP_TOTAL_ (PREP_W_ + PREP_WO_ + PREP_ROW_)

__global__ void k_prep_all(
    const int* __restrict__ sop, const float* __restrict__ matrix,
    const float* w3w, const float* w3u, const float* b3w, const float* b3u,
    const float* w4w, const float* w4u, const float* b4w, const float* b4u,
    const float* w5w, const float* w5u, const float* b5w, const float* b5u,
    const float* __restrict__ wo)
{
    int i = blockIdx.x*blockDim.x + threadIdx.x;
    if (i < PREP_W_) {
        int g = i / (H_*H_);
        int rem = i - g*(H_*H_);
        int h = rem / H_, k = rem - h*H_;
        const float* ww = (g==0) ? w3w : (g==1) ? w4w : w5w;
        const float* wu = (g==0) ? w3u : (g==1) ? w4u : w5u;
        g_weff[i] = rtf(ww[h*(2*H_) + k] + ww[h*(2*H_) + H_ + k]);
        g_ucat[i] = rtf(wu[rem]);
        if (i < 3*H_) {
            int gg = i / H_, h2 = i - gg*H_;
            const float* bw = (gg==0) ? b3w : (gg==1) ? b4w : b5w;
            const float* bu = (gg==0) ? b3u : (gg==1) ? b4u : b5u;
            g_bias[i] = bw[h2] + bu[h2];
        }
    } else if (i < PREP_W_ + PREP_WO_) {
        int j = i - PREP_W_;
        int row = j >> 10, col = j & 1023;
        int dst = (col < H_) ? row*H_ + col : (row + H_)*H_ + (col - H_);
        g_wor[dst] = rtf(wo[j]);
    } else if (i < PREP_TOTAL_) {
        int j = i - PREP_W_ - PREP_WO_;
        int r = j / C_, c = j - r*C_;
        g_row[j] = matrix[((size_t)sop[2*r]*NOBJ_ + sop[2*r+1])*C_ + c];
    }
}

__global__ void k_copy_in(const float* __restrict__ src) {
    int n = RN_*H_;
    for (int i = blockIdx.x*blockDim.x + threadIdx.x; i < n; i += gridDim.x*blockDim.x)
        g_inp[i] = rtf(src[i]);
}

// ================= av (writes tf32-rounded) =================
__global__ void k_av(const float* __restrict__ hid) {
    __shared__ float srow[C_];
    int r = blockIdx.y;
    if (threadIdx.x < C_) srow[threadIdx.x] = g_row[r*C_ + threadIdx.x];
    __syncthreads();
    int h = blockIdx.x*blockDim.x + threadIdx.x;
    const float* hb = hid  + (size_t)r*NODE_*H_;
    float*       ab = g_av + (size_t)r*NODE_*H_;
    float s01 = hb[h] + hb[H_ + h];
    float acc = 0.f;
    #pragma unroll 3
    for (int c = 0; c < C_; ++c) {
        float rc = srow[c];
        acc = fmaf(rc, hb[(2+c)*H_ + h], acc);
        ab[(2+c)*H_ + h] = rtf(rc * s01);
    }
    float accr = rtf(acc);
    ab[h]      = accr;
    ab[H_ + h] = accr;
}

// ================= tf32 mma GEMM: CTA 128x128, 4 warps, warp 64x64 ==========
#define ACT_GATE 1
#define ACT_GRU  2
#define ACT_RELU 3

#define STG_AFL   (128*36)
#define STG_FL    (2*STG_AFL)
#define STG_BYTES (STG_FL*4)               /* 36864  */
#define SMEM_BYTES (3*STG_BYTES)           /* 110592 */

template<int ACT>
__global__ void __launch_bounds__(128, 2) k_tmma(
    const float* __restrict__ A1, const float* __restrict__ W1,
    const float* __restrict__ A2, const float* __restrict__ W2,
    const float* __restrict__ bias,
    const float* __restrict__ hidin,   // GATE: f for rf; GRU: previous hidden
    const float* __restrict__ zbuf,    // GRU: zv (stride 512)
    float* __restrict__ Co)
{
    extern __shared__ __align__(16) float sm[];
    const uint32_t smem_base = smem_u32(sm);
    const int tid  = threadIdx.x;
    const int lane = tid & 31;
    const int wid  = tid >> 5;
    const int wm   = wid >> 1, wn = wid & 1;
    const int blockRow = blockIdx.y * 128;
    const int blockCol = blockIdx.x * 128;

    float acc[4][8][4];
    #pragma unroll
    for (int i = 0; i < 4; ++i)
        #pragma unroll
        for (int j = 0; j < 8; ++j)
            #pragma unroll
            for (int v = 0; v < 4; ++v) acc[i][j][v] = 0.f;

    const int mrow = tid >> 3;        // producer row base
    const int qk   = tid & 7;         // producer k-quad

    // ldmatrix per-lane byte offsets (within a stage)
    uint32_t aoff[4], boff[4];
    {
        const int rw = lane & 7;
        const int h8 = (lane >> 3) & 1;     // +8 rows for A / +4 k for B
        const int hi = lane >> 4;           // +4 k for A / +8 rows for B
        #pragma unroll
        for (int i = 0; i < 4; ++i)
            aoff[i] = ((wm*64 + i*16 + rw + h8*8)*36 + hi*4) * 4;
        #pragma unroll
        for (int jj = 0; jj < 4; ++jj)
            boff[jj] = (STG_AFL + (wn*64 + jj*16 + rw + hi*8)*36 + h8*4) * 4;
    }

    auto load_chunk = [&](int c, int stage) {
        const int term = c >> 4;
        const int kk0  = (c & 15) * 32;
        const float* A = term ? A2 : A1;
        const float* W = term ? W2 : W1;
        const float* Ag = A + (size_t)(blockRow + mrow)*512 + kk0 + qk*4;
        const float* Wg = W + (size_t)(blockCol + mrow)*512 + kk0 + qk*4;
        uint32_t sa = smem_base + stage*STG_BYTES + mrow*144 + qk*16;
        uint32_t sb = sa + STG_AFL*4;
        #pragma unroll
        for (int p = 0; p < 8; ++p) {
            cp_async16(sa + p*16*144, Ag + (size_t)p*16*512);
            cp_async16(sb + p*16*144, Wg + (size_t)p*16*512);
        }
    };

    auto compute = [&](int stage) {
        const uint32_t sbase = smem_base + stage*STG_BYTES;
        #pragma unroll
        for (int s = 0; s < 4; ++s) {
            uint32_t af[4][4], bf[4][4];
            #pragma unroll
            for (int i = 0; i < 4; ++i)  ldsm4(af[i],  sbase + aoff[i]  + s*32);
            #pragma unroll
            for (int jj = 0; jj < 4; ++jj) ldsm4(bf[jj], sbase + boff[jj] + s*32);
            #pragma unroll
            for (int i = 0; i < 4; ++i)
                #pragma unroll
                for (int jj = 0; jj < 4; ++jj) {
                    mma_tf32(acc[i][2*jj],   af[i], &bf[jj][0]);
                    mma_tf32(acc[i][2*jj+1], af[i], &bf[jj][2]);
                }
        }
    };

    const int NCH = 32;
    load_chunk(0, 0); CP_COMMIT();
    load_chunk(1, 1); CP_COMMIT();

    int stage_n = 2;
    for (int c = 0; c < NCH; ++c) {
        CP_WAIT(1);
        __syncthreads();
        if (c + 2 < NCH) load_chunk(c + 2, stage_n);
        CP_COMMIT();
        int stage_c = stage_n + 1; if (stage_c >= 3) stage_c -= 3;
        compute(stage_c);
        stage_n = stage_c;
    }
    CP_WAIT(0);

    // ---- epilogue
    #pragma unroll
    for (int i = 0; i < 4; ++i) {
        const int r0 = blockRow + wm*64 + i*16 + (lane >> 2);
        #pragma unroll
        for (int j = 0; j < 8; ++j) {
            const int gc = blockCol + wn*64 + j*8 + (lane & 3)*2;
            float2 bs = *(const float2*)&bias[gc];
            float v0 = acc[i][j][0] + bs.x;
            float v1 = acc[i][j][1] + bs.y;
            float v2 = acc[i][j][2] + bs.x;
            float v3 = acc[i][j][3] + bs.y;
            if (ACT == ACT_GATE) {
                float s0 = 1.f/(1.f+__expf(-v0)), s1 = 1.f/(1.f+__expf(-v1));
                float s2 = 1.f/(1.f+__expf(-v2)), s3 = 1.f/(1.f+__expf(-v3));
                if (gc < 512) {
                    *(float2*)&Co[(size_t)r0*512 + gc]     = make_float2(s0, s1);
                    *(float2*)&Co[(size_t)(r0+8)*512 + gc] = make_float2(s2, s3);
                } else {
                    const int hc = gc - 512;
                    float2 f0 = *(const float2*)&hidin[(size_t)r0*512 + hc];
                    float2 f1 = *(const float2*)&hidin[(size_t)(r0+8)*512 + hc];
                    *(float2*)&g_rf[(size_t)r0*512 + hc]     = make_float2(rtf(s0*f0.x), rtf(s1*f0.y));
                    *(float2*)&g_rf[(size_t)(r0+8)*512 + hc] = make_float2(rtf(s2*f1.x), rtf(s3*f1.y));
                }
            } else if (ACT == ACT_RELU) {
                *(float2*)&Co[(size_t)r0*512 + gc]     = make_float2(fmaxf(v0,0.f), fmaxf(v1,0.f));
                *(float2*)&Co[(size_t)(r0+8)*512 + gc] = make_float2(fmaxf(v2,0.f), fmaxf(v3,0.f));
            } else {  // GRU
                float2 z0 = *(const float2*)&zbuf [(size_t)r0*512 + gc];
                float2 f0 = *(const float2*)&hidin[(size_t)r0*512 + gc];
                float2 z1 = *(const float2*)&zbuf [(size_t)(r0+8)*512 + gc];
                float2 f1 = *(const float2*)&hidin[(size_t)(r0+8)*512 + gc];
                float o0 = (1.f-z0.x)*f0.x + z0.x*tanhf(v0);
                float o1 = (1.f-z0.y)*f0.y + z0.y*tanhf(v1);
                float o2 = (1.f-z1.x)*f1.x + z1.x*tanhf(v2);
                float o3 = (1.f-z1.y)*f1.y + z1.y*tanhf(v3);
                *(float2*)&Co[(size_t)r0*512 + gc]     = make_float2(rtf(o0), rtf(o1));
                *(float2*)&Co[(size_t)(r0+8)*512 + gc] = make_float2(rtf(o2), rtf(o3));
            }
        }
    }
}

// ================= FFMA split-K GEMM (final skinny GEMM, exact fp32) =========
__global__ void __launch_bounds__(256) k_gemm_ffma(
    const float* __restrict__ A1, int lda1, const float* __restrict__ W1, int ldw1,
    float* __restrict__ Co, int ldc, int M, int N, int K)
{
    __shared__ __align__(16) float As[16][128];
    __shared__ __align__(16) float Ws[16][64];
    const int tx = threadIdx.x & 15;
    const int ty = threadIdx.x >> 4;
    const int blockRow = blockIdx.y * 128;
    const int blockCol = blockIdx.x * 64;
    int kbeg = blockIdx.z * KSLICE_;
    int kend = kbeg + KSLICE_;
    float acc[8][4];
    #pragma unroll
    for (int i = 0; i < 8; ++i)
        #pragma unroll
        for (int j = 0; j < 4; ++j) acc[i][j] = 0.f;
    for (int k0 = kbeg; k0 < kend; k0 += 16) {
        #pragma unroll
        for (int t = 0; t < 2; ++t) {
            int l = threadIdx.x + t*256;
            int m = l >> 2, kv = (l & 3) << 2;
            float4 v = *(const float4*)&A1[(size_t)(blockRow + m)*lda1 + k0 + kv];
            As[kv+0][m] = v.x; As[kv+1][m] = v.y; As[kv+2][m] = v.z; As[kv+3][m] = v.w;
        }
        {
            int n = threadIdx.x >> 2, kv = (threadIdx.x & 3) << 2;
            int gn = blockCol + n;
            float4 v = make_float4(0.f,0.f,0.f,0.f);
            if (gn < N) v = *(const float4*)&W1[(size_t)gn*ldw1 + k0 + kv];
            Ws[kv+0][n] = v.x; Ws[kv+1][n] = v.y; Ws[kv+2][n] = v.z; Ws[kv+3][n] = v.w;
        }
        __syncthreads();
        #pragma unroll
        for (int kk = 0; kk < 16; ++kk) {
            float a[8], bv[4];
            *(float4*)&a[0] = *(const float4*)&As[kk][ty*8];
            *(float4*)&a[4] = *(const float4*)&As[kk][ty*8+4];
            *(float4*)&bv[0] = *(const float4*)&Ws[kk][tx*4];
            #pragma unroll
            for (int i = 0; i < 8; ++i)
                #pragma unroll
                for (int j = 0; j < 4; ++j)
                    acc[i][j] = fmaf(a[i], bv[j], acc[i][j]);
        }
        __syncthreads();
    }
    size_t outBase = (size_t)blockIdx.z * (size_t)M * ldc;
    #pragma unroll
    for (int i = 0; i < 8; ++i) {
        int gmm = blockRow + ty*8 + i;
        #pragma unroll
        for (int j = 0; j < 4; ++j) {
            int gn = blockCol + tx*4 + j;
            if (gn < N) Co[outBase + (size_t)gmm*ldc + gn] = acc[i][j];
        }
    }
}

__global__ void k_reduce(const float* __restrict__ bc, float* __restrict__ out) {
    int i = blockIdx.x*blockDim.x + threadIdx.x;
    if (i >= R_*C_) return;
    float s = bc[i % C_];
    #pragma unroll
    for (int z = 0; z < SPLITS_; ++z) s += g_part[(size_t)z*R_*C_ + i];
    out[i] = s;
}

// ================= launch =================
extern "C" void kernel_launch(void* const* d_in, const int* in_sizes, int n_in,
                              void* d_out, int out_size) {
    const int*   sop    = (const int*)  d_in[1];
    const float* input  = (const float*)d_in[2];
    const float* matrix = (const float*)d_in[4];
    const float* w3w = (const float*)d_in[5];  const float* b3w = (const float*)d_in[6];
    const float* w3u = (const float*)d_in[7];  const float* b3u = (const float*)d_in[8];
    const float* w4w = (const float*)d_in[9];  const float* b4w = (const float*)d_in[10];
    const float* w4u = (const float*)d_in[11]; const float* b4u = (const float*)d_in[12];
    const float* w5w = (const float*)d_in[13]; const float* b5w = (const float*)d_in[14];
    const float* w5u = (const float*)d_in[15]; const float* b5u = (const float*)d_in[16];
    const float* wo  = (const float*)d_in[17]; const float* bo  = (const float*)d_in[18];
    const float* wc  = (const float*)d_in[19]; const float* bc  = (const float*)d_in[20];
    float* out = (float*)d_out;

    float *p_h0, *p_h1, *p_inp, *p_av, *p_z, *p_rf, *p_out, *p_weff, *p_ucat, *p_wor, *p_bias, *p_part;
    cudaGetSymbolAddress((void**)&p_h0,   g_hid0);
    cudaGetSymbolAddress((void**)&p_h1,   g_hid1);
    cudaGetSymbolAddress((void**)&p_inp,  g_inp);
    cudaGetSymbolAddress((void**)&p_av,   g_av);
    cudaGetSymbolAddress((void**)&p_z,    g_z);
    cudaGetSymbolAddress((void**)&p_rf,   g_rf);
    cudaGetSymbolAddress((void**)&p_out,  g_out);
    cudaGetSymbolAddress((void**)&p_weff, g_weff);
    cudaGetSymbolAddress((void**)&p_ucat, g_ucat);
    cudaGetSymbolAddress((void**)&p_wor,  g_wor);
    cudaGetSymbolAddress((void**)&p_bias, g_bias);
    cudaGetSymbolAddress((void**)&p_part, g_part);

    cudaFuncSetAttribute(k_tmma<ACT_GATE>, cudaFuncAttributeMaxDynamicSharedMemorySize, SMEM_BYTES);
    cudaFuncSetAttribute(k_tmma<ACT_GRU>,  cudaFuncAttributeMaxDynamicSharedMemorySize, SMEM_BYTES);
    cudaFuncSetAttribute(k_tmma<ACT_RELU>, cudaFuncAttributeMaxDynamicSharedMemorySize, SMEM_BYTES);

    k_prep_all<<<(PREP_TOTAL_ + 255)/256, 256>>>(sop, matrix,
        w3w, w3u, b3w, b3u, w4w, w4u, b4w, b4u, w5w, w5u, b5w, b5u, wo);
    k_copy_in<<<2048, 256>>>(input);

    dim3 gGate(1024/128, RN_/128);
    dim3 gHv  (512/128,  RN_/128);

    // t=0 hidden IS the rounded input (g_inp); GRU never writes g_inp.
    float* hin  = p_inp;
    float* houts[3] = {p_h0, p_h1, p_h0};
    for (int t = 0; t < T_; ++t) {
        float* hout = houts[t];
        k_av<<<dim3(2, R_), 256>>>(hin);
        k_tmma<ACT_GATE><<<gGate, 128, SMEM_BYTES>>>(
            p_av, p_weff, hin, p_ucat, p_bias, hin, nullptr, p_z);
        k_tmma<ACT_GRU><<<gHv, 128, SMEM_BYTES>>>(
            p_av, p_weff + 2*H_*H_, p_rf, p_ucat + 2*H_*H_, p_bias + 2*H_,
            hin, p_z, hout);
        hin = hout;
    }

    // out = relu(fh@wo[:, :H].T + input@wo[:, H:].T + bo)
    k_tmma<ACT_RELU><<<gHv, 128, SMEM_BYTES>>>(
        hin, p_wor, p_inp, p_wor + H_*H_, bo, nullptr, nullptr, p_out);

    // rel_dists = out.reshape(R, 27136) @ wc.T + bc
    k_gemm_ffma<<<dim3(1, R_/128, SPLITS_), 256>>>(
        p_out, K2_, wc, K2_, p_part, C_, R_, C_, K2_);
    k_reduce<<<(R_*C_ + 255)/256, 256>>>(bc, out);
}

// round 6
// speedup vs baseline: 5.0018x; 1.3748x over previous
#include <cuda_runtime.h>
#include <math.h>
#include <stdint.h>

#define R_    2048
#define NODE_ 53
#define H_    512
#define C_    51
#define NOBJ_ 151
#define OUT_  512
#define T_    3
#define RN_   (R_*NODE_)      /* 108544 */
#define K2_   (NODE_*OUT_)    /* 27136  */
#define SPLITS_ 32
#define KSLICE_ (K2_/SPLITS_) /* 848 */

// ================= tf32 / mma helpers =================
__device__ __forceinline__ uint32_t f2tf32(float x) {
    uint32_t u;
    asm("cvt.rna.tf32.f32 %0, %1;" : "=r"(u) : "f"(x));
    return u;
}
__device__ __forceinline__ float rtf(float x) { return __uint_as_float(f2tf32(x)); }

__device__ __forceinline__ void mma_tf32(float* d, const uint32_t* a, const uint32_t* b) {
    asm volatile(
        "mma.sync.aligned.m16n8k8.row.col.f32.tf32.tf32.f32 "
        "{%0,%1,%2,%3}, {%4,%5,%6,%7}, {%8,%9}, {%0,%1,%2,%3};\n"
        : "+f"(d[0]), "+f"(d[1]), "+f"(d[2]), "+f"(d[3])
        : "r"(a[0]), "r"(a[1]), "r"(a[2]), "r"(a[3]), "r"(b[0]), "r"(b[1]));
}
__device__ __forceinline__ void ldsm4(uint32_t* r, uint32_t addr) {
    asm volatile("ldmatrix.sync.aligned.m8n8.x4.shared.b16 {%0,%1,%2,%3}, [%4];"
        : "=r"(r[0]), "=r"(r[1]), "=r"(r[2]), "=r"(r[3]) : "r"(addr));
}
__device__ __forceinline__ uint32_t smem_u32(const void* p) {
    uint32_t a;
    asm("{ .reg .u64 t; cvta.to.shared.u64 t, %1; cvt.u32.u64 %0, t; }" : "=r"(a) : "l"(p));
    return a;
}
__device__ __forceinline__ void cp_async16(uint32_t s, const void* g) {
    asm volatile("cp.async.cg.shared.global [%0], [%1], 16;" :: "r"(s), "l"(g));
}
#define CP_COMMIT() asm volatile("cp.async.commit_group;" ::: "memory")
#define CP_WAIT(n)  asm volatile("cp.async.wait_group %0;" :: "n"(n) : "memory")

// ================= scratch =================
__device__ float g_hid0 [RN_*H_];
__device__ float g_hid1 [RN_*H_];
__device__ float g_inp  [RN_*H_];       // tf32-rounded input == initial hidden
__device__ float g_sa   [2*R_*H_];      // [acc rows | s01 rows], tf32-rounded
__device__ float g_Y    [2*R_*3*H_];    // Y = g_sa @ [W3e;W4e;W5e]^T  (4096 x 1536)
__device__ float g_z    [RN_*H_];       // zv
__device__ float g_rf   [RN_*H_];       // tf32(rv * f)
__device__ float g_out  [RN_*OUT_];
__device__ float g_weff [3*H_*H_];
__device__ float g_ucat [3*H_*H_];
__device__ float g_wor  [2*H_*H_];
__device__ float g_bias [3*H_];
__device__ float g_row  [R_*C_];
__device__ float g_coef [RN_];
__device__ int   g_yrow [RN_];
__device__ float g_part [SPLITS_*R_*C_];

// ================= combined prep =================
#define PREP_W_   (3*H_*H_)
#define PREP_WO_  (2*H_*H_)
#define PREP_ROW_ (R_*C_)
#define PREP_CY_  (RN_)
#define PREP_TOTAL_ (PREP_W_ + PREP_WO_ + PREP_ROW_ + PREP_CY_)

__global__ void k_prep_all(
    const int* __restrict__ sop, const float* __restrict__ matrix,
    const float* w3w, const float* w3u, const float* b3w, const float* b3u,
    const float* w4w, const float* w4u, const float* b4w, const float* b4u,
    const float* w5w, const float* w5u, const float* b5w, const float* b5u,
    const float* __restrict__ wo)
{
    int i = blockIdx.x*blockDim.x + threadIdx.x;
    if (i < PREP_W_) {
        int g = i / (H_*H_);
        int rem = i - g*(H_*H_);
        int h = rem / H_, k = rem - h*H_;
        const float* ww = (g==0) ? w3w : (g==1) ? w4w : w5w;
        const float* wu = (g==0) ? w3u : (g==1) ? w4u : w5u;
        g_weff[i] = rtf(ww[h*(2*H_) + k] + ww[h*(2*H_) + H_ + k]);
        g_ucat[i] = rtf(wu[rem]);
        if (i < 3*H_) {
            int gg = i / H_, h2 = i - gg*H_;
            const float* bw = (gg==0) ? b3w : (gg==1) ? b4w : b5w;
            const float* bu = (gg==0) ? b3u : (gg==1) ? b4u : b5u;
            g_bias[i] = bw[h2] + bu[h2];
        }
    } else if (i < PREP_W_ + PREP_WO_) {
        int j = i - PREP_W_;
        int row = j >> 10, col = j & 1023;
        int dst = (col < H_) ? row*H_ + col : (row + H_)*H_ + (col - H_);
        g_wor[dst] = rtf(wo[j]);
    } else if (i < PREP_W_ + PREP_WO_ + PREP_ROW_) {
        int j = i - PREP_W_ - PREP_WO_;
        int r = j / C_, c = j - r*C_;
        g_row[j] = matrix[((size_t)sop[2*r]*NOBJ_ + sop[2*r+1])*C_ + c];
    } else if (i < PREP_TOTAL_) {
        int j = i - PREP_W_ - PREP_WO_ - PREP_ROW_;
        int r = j / NODE_, e = j - r*NODE_;
        if (e < 2) { g_coef[j] = 1.f; g_yrow[j] = r; }
        else {
            g_coef[j] = matrix[((size_t)sop[2*r]*NOBJ_ + sop[2*r+1])*C_ + (e-2)];
            g_yrow[j] = R_ + r;
        }
    }
}

__global__ void k_copy_in(const float* __restrict__ src) {
    int n = RN_*H_;
    for (int i = blockIdx.x*blockDim.x + threadIdx.x; i < n; i += gridDim.x*blockDim.x)
        g_inp[i] = rtf(src[i]);
}

// ================= av: per-relation acc & s01 vectors ======================
__global__ void k_av(const float* __restrict__ hid) {
    __shared__ float srow[C_];
    int r = blockIdx.y;
    if (threadIdx.x < C_) srow[threadIdx.x] = g_row[r*C_ + threadIdx.x];
    __syncthreads();
    int h = blockIdx.x*blockDim.x + threadIdx.x;
    const float* hb = hid + (size_t)r*NODE_*H_;
    float s01 = hb[h] + hb[H_ + h];
    float acc = 0.f;
    #pragma unroll 3
    for (int c = 0; c < C_; ++c)
        acc = fmaf(srow[c], hb[(2+c)*H_ + h], acc);
    g_sa[(size_t)r*H_ + h]        = rtf(acc);
    g_sa[(size_t)(R_+r)*H_ + h]   = rtf(s01);
}

// ================= tf32 mma GEMM: CTA 128x128, 4 warps, warp 64x64 ==========
#define ACT_NONE 0
#define ACT_GATE 1
#define ACT_GRU  2
#define ACT_RELU 3

#define STG_AFL   (128*36)
#define STG_FL    (2*STG_AFL)
#define STG_BYTES (STG_FL*4)               /* 36864  */
#define SMEM_BYTES (3*STG_BYTES)           /* 110592 */

template<int ACT, int NTERMS>
__global__ void __launch_bounds__(128, 2) k_tmma(
    const float* __restrict__ A1, const float* __restrict__ W1,
    const float* __restrict__ A2, const float* __restrict__ W2,
    const float* __restrict__ bias,
    const float* __restrict__ hidin,   // GATE: f for rf; GRU: previous hidden
    const float* __restrict__ zbuf,    // GRU: zv (stride 512)
    int ycol0,                          // Y column offset (GATE 0, GRU 1024)
    float* __restrict__ Co, int ldc)
{
    extern __shared__ __align__(16) float sm[];
    const uint32_t smem_base = smem_u32(sm);
    const int tid  = threadIdx.x;
    const int lane = tid & 31;
    const int wid  = tid >> 5;
    const int wm   = wid >> 1, wn = wid & 1;
    const int blockRow = blockIdx.y * 128;
    const int blockCol = blockIdx.x * 128;

    float acc[4][8][4];
    #pragma unroll
    for (int i = 0; i < 4; ++i)
        #pragma unroll
        for (int j = 0; j < 8; ++j)
            #pragma unroll
            for (int v = 0; v < 4; ++v) acc[i][j][v] = 0.f;

    const int mrow = tid >> 3;
    const int qk   = tid & 7;

    uint32_t aoff[4], boff[4];
    {
        const int rw = lane & 7;
        const int h8 = (lane >> 3) & 1;
        const int hi = lane >> 4;
        #pragma unroll
        for (int i = 0; i < 4; ++i)
            aoff[i] = ((wm*64 + i*16 + rw + h8*8)*36 + hi*4) * 4;
        #pragma unroll
        for (int jj = 0; jj < 4; ++jj)
            boff[jj] = (STG_AFL + (wn*64 + jj*16 + rw + hi*8)*36 + h8*4) * 4;
    }

    auto load_chunk = [&](int c, int stage) {
        const int term = c >> 4;
        const int kk0  = (c & 15) * 32;
        const float* A = term ? A2 : A1;
        const float* W = term ? W2 : W1;
        const float* Ag = A + (size_t)(blockRow + mrow)*512 + kk0 + qk*4;
        const float* Wg = W + (size_t)(blockCol + mrow)*512 + kk0 + qk*4;
        uint32_t sa = smem_base + stage*STG_BYTES + mrow*144 + qk*16;
        uint32_t sb = sa + STG_AFL*4;
        #pragma unroll
        for (int p = 0; p < 8; ++p) {
            cp_async16(sa + p*16*144, Ag + (size_t)p*16*512);
            cp_async16(sb + p*16*144, Wg + (size_t)p*16*512);
        }
    };

    auto compute = [&](int stage) {
        const uint32_t sbase = smem_base + stage*STG_BYTES;
        #pragma unroll
        for (int s = 0; s < 4; ++s) {
            uint32_t af[4][4], bf[4][4];
            #pragma unroll
            for (int i = 0; i < 4; ++i)  ldsm4(af[i],  sbase + aoff[i]  + s*32);
            #pragma unroll
            for (int jj = 0; jj < 4; ++jj) ldsm4(bf[jj], sbase + boff[jj] + s*32);
            #pragma unroll
            for (int i = 0; i < 4; ++i)
                #pragma unroll
                for (int jj = 0; jj < 4; ++jj) {
                    mma_tf32(acc[i][2*jj],   af[i], &bf[jj][0]);
                    mma_tf32(acc[i][2*jj+1], af[i], &bf[jj][2]);
                }
        }
    };

    const int NCH = 16*NTERMS;
    load_chunk(0, 0); CP_COMMIT();
    load_chunk(1, 1); CP_COMMIT();

    int stage_n = 2;
    for (int c = 0; c < NCH; ++c) {
        CP_WAIT(1);
        __syncthreads();
        if (c + 2 < NCH) load_chunk(c + 2, stage_n);
        CP_COMMIT();
        int stage_c = stage_n + 1; if (stage_c >= 3) stage_c -= 3;
        compute(stage_c);
        stage_n = stage_c;
    }
    CP_WAIT(0);

    // ---- epilogue
    #pragma unroll
    for (int i = 0; i < 4; ++i) {
        const int r0 = blockRow + wm*64 + i*16 + (lane >> 2);
        float cf0 = 0.f, cf1 = 0.f;
        const float *y0p = nullptr, *y1p = nullptr;
        if (ACT == ACT_GATE || ACT == ACT_GRU) {
            cf0 = g_coef[r0];     y0p = g_Y + (size_t)g_yrow[r0]*1536   + ycol0;
            cf1 = g_coef[r0+8];   y1p = g_Y + (size_t)g_yrow[r0+8]*1536 + ycol0;
        }
        #pragma unroll
        for (int j = 0; j < 8; ++j) {
            const int gc = blockCol + wn*64 + j*8 + (lane & 3)*2;
            float v0 = acc[i][j][0];
            float v1 = acc[i][j][1];
            float v2 = acc[i][j][2];
            float v3 = acc[i][j][3];
            if (ACT != ACT_NONE) {
                float2 bs = *(const float2*)&bias[gc];
                v0 += bs.x; v1 += bs.y; v2 += bs.x; v3 += bs.y;
            }
            if (ACT == ACT_GATE || ACT == ACT_GRU) {
                float2 y0 = *(const float2*)&y0p[gc];
                float2 y1 = *(const float2*)&y1p[gc];
                v0 = fmaf(cf0, y0.x, v0); v1 = fmaf(cf0, y0.y, v1);
                v2 = fmaf(cf1, y1.x, v2); v3 = fmaf(cf1, y1.y, v3);
            }
            if (ACT == ACT_NONE) {
                *(float2*)&Co[(size_t)r0*ldc + gc]     = make_float2(v0, v1);
                *(float2*)&Co[(size_t)(r0+8)*ldc + gc] = make_float2(v2, v3);
            } else if (ACT == ACT_GATE) {
                float s0 = 1.f/(1.f+__expf(-v0)), s1 = 1.f/(1.f+__expf(-v1));
                float s2 = 1.f/(1.f+__expf(-v2)), s3 = 1.f/(1.f+__expf(-v3));
                if (gc < 512) {
                    *(float2*)&Co[(size_t)r0*512 + gc]     = make_float2(s0, s1);
                    *(float2*)&Co[(size_t)(r0+8)*512 + gc] = make_float2(s2, s3);
                } else {
                    const int hc = gc - 512;
                    float2 f0 = *(const float2*)&hidin[(size_t)r0*512 + hc];
                    float2 f1 = *(const float2*)&hidin[(size_t)(r0+8)*512 + hc];
                    *(float2*)&g_rf[(size_t)r0*512 + hc]     = make_float2(rtf(s0*f0.x), rtf(s1*f0.y));
                    *(float2*)&g_rf[(size_t)(r0+8)*512 + hc] = make_float2(rtf(s2*f1.x), rtf(s3*f1.y));
                }
            } else if (ACT == ACT_RELU) {
                *(float2*)&Co[(size_t)r0*512 + gc]     = make_float2(fmaxf(v0,0.f), fmaxf(v1,0.f));
                *(float2*)&Co[(size_t)(r0+8)*512 + gc] = make_float2(fmaxf(v2,0.f), fmaxf(v3,0.f));
            } else {  // GRU
                float2 z0 = *(const float2*)&zbuf [(size_t)r0*512 + gc];
                float2 f0 = *(const float2*)&hidin[(size_t)r0*512 + gc];
                float2 z1 = *(const float2*)&zbuf [(size_t)(r0+8)*512 + gc];
                float2 f1 = *(const float2*)&hidin[(size_t)(r0+8)*512 + gc];
                float o0 = (1.f-z0.x)*f0.x + z0.x*tanhf(v0);
                float o1 = (1.f-z0.y)*f0.y + z0.y*tanhf(v1);
                float o2 = (1.f-z1.x)*f1.x + z1.x*tanhf(v2);
                float o3 = (1.f-z1.y)*f1.y + z1.y*tanhf(v3);
                *(float2*)&Co[(size_t)r0*512 + gc]     = make_float2(rtf(o0), rtf(o1));
                *(float2*)&Co[(size_t)(r0+8)*512 + gc] = make_float2(rtf(o2), rtf(o3));
            }
        }
    }
}

// ================= FFMA split-K GEMM (final skinny GEMM, exact fp32) =========
__global__ void __launch_bounds__(256) k_gemm_ffma(
    const float* __restrict__ A1, int lda1, const float* __restrict__ W1, int ldw1,
    float* __restrict__ Co, int ldc, int M, int N, int K)
{
    __shared__ __align__(16) float As[16][128];
    __shared__ __align__(16) float Ws[16][64];
    const int tx = threadIdx.x & 15;
    const int ty = threadIdx.x >> 4;
    const int blockRow = blockIdx.y * 128;
    const int blockCol = blockIdx.x * 64;
    int kbeg = blockIdx.z * KSLICE_;
    int kend = kbeg + KSLICE_;
    float acc[8][4];
    #pragma unroll
    for (int i = 0; i < 8; ++i)
        #pragma unroll
        for (int j = 0; j < 4; ++j) acc[i][j] = 0.f;
    for (int k0 = kbeg; k0 < kend; k0 += 16) {
        #pragma unroll
        for (int t = 0; t < 2; ++t) {
            int l = threadIdx.x + t*256;
            int m = l >> 2, kv = (l & 3) << 2;
            float4 v = *(const float4*)&A1[(size_t)(blockRow + m)*lda1 + k0 + kv];
            As[kv+0][m] = v.x; As[kv+1][m] = v.y; As[kv+2][m] = v.z; As[kv+3][m] = v.w;
        }
        {
            int n = threadIdx.x >> 2, kv = (threadIdx.x & 3) << 2;
            int gn = blockCol + n;
            float4 v = make_float4(0.f,0.f,0.f,0.f);
            if (gn < N) v = *(const float4*)&W1[(size_t)gn*ldw1 + k0 + kv];
            Ws[kv+0][n] = v.x; Ws[kv+1][n] = v.y; Ws[kv+2][n] = v.z; Ws[kv+3][n] = v.w;
        }
        __syncthreads();
        #pragma unroll
        for (int kk = 0; kk < 16; ++kk) {
            float a[8], bv[4];
            *(float4*)&a[0] = *(const float4*)&As[kk][ty*8];
            *(float4*)&a[4] = *(const float4*)&As[kk][ty*8+4];
            *(float4*)&bv[0] = *(const float4*)&Ws[kk][tx*4];
            #pragma unroll
            for (int i = 0; i < 8; ++i)
                #pragma unroll
                for (int j = 0; j < 4; ++j)
                    acc[i][j] = fmaf(a[i], bv[j], acc[i][j]);
        }
        __syncthreads();
    }
    size_t outBase = (size_t)blockIdx.z * (size_t)M * ldc;
    #pragma unroll
    for (int i = 0; i < 8; ++i) {
        int gmm = blockRow + ty*8 + i;
        #pragma unroll
        for (int j = 0; j < 4; ++j) {
            int gn = blockCol + tx*4 + j;
            if (gn < N) Co[outBase + (size_t)gmm*ldc + gn] = acc[i][j];
        }
    }
}

__global__ void k_reduce(const float* __restrict__ bc, float* __restrict__ out) {
    int i = blockIdx.x*blockDim.x + threadIdx.x;
    if (i >= R_*C_) return;
    float s = bc[i % C_];
    #pragma unroll
    for (int z = 0; z < SPLITS_; ++z) s += g_part[(size_t)z*R_*C_ + i];
    out[i] = s;
}

// ================= launch =================
extern "C" void kernel_launch(void* const* d_in, const int* in_sizes, int n_in,
                              void* d_out, int out_size) {
    const int*   sop    = (const int*)  d_in[1];
    const float* input  = (const float*)d_in[2];
    const float* matrix = (const float*)d_in[4];
    const float* w3w = (const float*)d_in[5];  const float* b3w = (const float*)d_in[6];
    const float* w3u = (const float*)d_in[7];  const float* b3u = (const float*)d_in[8];
    const float* w4w = (const float*)d_in[9];  const float* b4w = (const float*)d_in[10];
    const float* w4u = (const float*)d_in[11]; const float* b4u = (const float*)d_in[12];
    const float* w5w = (const float*)d_in[13]; const float* b5w = (const float*)d_in[14];
    const float* w5u = (const float*)d_in[15]; const float* b5u = (const float*)d_in[16];
    const float* wo  = (const float*)d_in[17]; const float* bo  = (const float*)d_in[18];
    const float* wc  = (const float*)d_in[19]; const float* bc  = (const float*)d_in[20];
    float* out = (float*)d_out;

    float *p_h0, *p_h1, *p_inp, *p_sa, *p_Y, *p_z, *p_rf, *p_out, *p_weff, *p_ucat, *p_wor, *p_bias, *p_part;
    cudaGetSymbolAddress((void**)&p_h0,   g_hid0);
    cudaGetSymbolAddress((void**)&p_h1,   g_hid1);
    cudaGetSymbolAddress((void**)&p_inp,  g_inp);
    cudaGetSymbolAddress((void**)&p_sa,   g_sa);
    cudaGetSymbolAddress((void**)&p_Y,    g_Y);
    cudaGetSymbolAddress((void**)&p_z,    g_z);
    cudaGetSymbolAddress((void**)&p_rf,   g_rf);
    cudaGetSymbolAddress((void**)&p_out,  g_out);
    cudaGetSymbolAddress((void**)&p_weff, g_weff);
    cudaGetSymbolAddress((void**)&p_ucat, g_ucat);
    cudaGetSymbolAddress((void**)&p_wor,  g_wor);
    cudaGetSymbolAddress((void**)&p_bias, g_bias);
    cudaGetSymbolAddress((void**)&p_part, g_part);

    cudaFuncSetAttribute(k_tmma<ACT_NONE,1>, cudaFuncAttributeMaxDynamicSharedMemorySize, SMEM_BYTES);
    cudaFuncSetAttribute(k_tmma<ACT_GATE,1>, cudaFuncAttributeMaxDynamicSharedMemorySize, SMEM_BYTES);
    cudaFuncSetAttribute(k_tmma<ACT_GRU,1>,  cudaFuncAttributeMaxDynamicSharedMemorySize, SMEM_BYTES);
    cudaFuncSetAttribute(k_tmma<ACT_RELU,2>, cudaFuncAttributeMaxDynamicSharedMemorySize, SMEM_BYTES);

    k_prep_all<<<(PREP_TOTAL_ + 255)/256, 256>>>(sop, matrix,
        w3w, w3u, b3w, b3u, w4w, w4u, b4w, b4u, w5w, w5u, b5w, b5u, wo);
    k_copy_in<<<2048, 256>>>(input);

    dim3 gY   (1536/128, 2*R_/128);  // 12 x 32
    dim3 gGate(1024/128, RN_/128);   // 8 x 848
    dim3 gHv  (512/128,  RN_/128);   // 4 x 848

    float* hin  = p_inp;             // t=0 hidden IS the rounded input
    float* houts[3] = {p_h0, p_h1, p_h0};
    for (int t = 0; t < T_; ++t) {
        float* hout = houts[t];
        k_av<<<dim3(2, R_), 256>>>(hin);
        // Y = [acc; s01] @ [W3e;W4e;W5e]^T   (4096 x 1536, K=512)
        k_tmma<ACT_NONE,1><<<gY, 128, SMEM_BYTES>>>(
            p_sa, p_weff, nullptr, nullptr, nullptr, nullptr, nullptr, 0, p_Y, 1536);
        // gates: sigmoid(fh@[w3u;w4u]^T + coef*Y[:,0:1024] + bias) -> z | rf
        k_tmma<ACT_GATE,1><<<gGate, 128, SMEM_BYTES>>>(
            hin, p_ucat, nullptr, nullptr, p_bias, hin, nullptr, 0, p_z, 512);
        // hidden' = (1-z)*f + z*tanh(rf@w5u^T + coef*Y[:,1024:1536] + b5)
        k_tmma<ACT_GRU,1><<<gHv, 128, SMEM_BYTES>>>(
            p_rf, p_ucat + 2*H_*H_, nullptr, nullptr, p_bias + 2*H_,
            hin, p_z, 1024, hout, 512);
        hin = hout;
    }

    // out = relu(fh@wo[:, :H].T + input@wo[:, H:].T + bo)
    k_tmma<ACT_RELU,2><<<gHv, 128, SMEM_BYTES>>>(
        hin, p_wor, p_inp, p_wor + H_*H_, bo, nullptr, nullptr, 0, p_out, 512);

    // rel_dists = out.reshape(R, 27136) @ wc.T + bc
    k_gemm_ffma<<<dim3(1, R_/128, SPLITS_), 256>>>(
        p_out, K2_, wc, K2_, p_part, C_, R_, C_, K2_);
    k_reduce<<<(R_*C_ + 255)/256, 256>>>(bc, out);
}

// round 8
// speedup vs baseline: 7.6416x; 1.5278x over previous
#include <cuda_runtime.h>
#include <cuda_fp16.h>
#include <math.h>
#include <stdint.h>

#define R_    2048
#define NODE_ 53
#define H_    512
#define C_    51
#define NOBJ_ 151
#define T_    3
#define RN_   (R_*NODE_)      /* 108544 */
#define K2_   (NODE_*512)     /* 27136  */
#define SPLITS_ 53            /* 424 chunks of 64 / 8 per slice */

// ================= helpers =================
__device__ __forceinline__ void mma_f16(float* d, const uint32_t* a, const uint32_t* b) {
    asm volatile(
        "mma.sync.aligned.m16n8k16.row.col.f32.f16.f16.f32 "
        "{%0,%1,%2,%3}, {%4,%5,%6,%7}, {%8,%9}, {%0,%1,%2,%3};\n"
        : "+f"(d[0]), "+f"(d[1]), "+f"(d[2]), "+f"(d[3])
        : "r"(a[0]), "r"(a[1]), "r"(a[2]), "r"(a[3]), "r"(b[0]), "r"(b[1]));
}
__device__ __forceinline__ void ldsm4(uint32_t* r, uint32_t addr) {
    asm volatile("ldmatrix.sync.aligned.m8n8.x4.shared.b16 {%0,%1,%2,%3}, [%4];"
        : "=r"(r[0]), "=r"(r[1]), "=r"(r[2]), "=r"(r[3]) : "r"(addr));
}
__device__ __forceinline__ uint32_t smem_u32(const void* p) {
    uint32_t a;
    asm("{ .reg .u64 t; cvta.to.shared.u64 t, %1; cvt.u32.u64 %0, t; }" : "=r"(a) : "l"(p));
    return a;
}
__device__ __forceinline__ void cp_async16(uint32_t s, const void* g) {
    asm volatile("cp.async.cg.shared.global [%0], [%1], 16;" :: "r"(s), "l"(g));
}
#define CP_COMMIT() asm volatile("cp.async.commit_group;" ::: "memory")
#define CP_WAIT(n)  asm volatile("cp.async.wait_group %0;" :: "n"(n) : "memory")

// ================= scratch =================
__device__ __half g_hid0 [RN_*H_];
__device__ __half g_hid1 [RN_*H_];
__device__ __half g_inp  [RN_*H_];       // fp16 input == initial hidden
__device__ __half g_sa   [2*R_*H_];      // [acc rows | s01 rows]
__device__ __half g_rf   [RN_*H_];       // half(rv * f)
__device__ __half g_out  [RN_*H_];       // relu output (== (R, 27136) view)
__device__ __half g_weff [3*H_*H_];
__device__ __half g_ucat [3*H_*H_];
__device__ __half g_wor  [2*H_*H_];
__device__ __half g_wc   [128*K2_];      // wc padded to 128 rows (51..127 = 0)
__device__ float  g_z    [RN_*H_];       // zv (fp32 for update precision)
__device__ float  g_Y    [2*R_*3*H_];    // Y = sa @ [W3e;W4e;W5e]^T (4096 x 1536)
__device__ float  g_bias [3*H_];
__device__ float  g_row  [R_*C_];
__device__ float  g_coef [RN_];
__device__ int    g_yrow [RN_];
__device__ float  g_part [SPLITS_*R_*C_];

// ================= combined prep =================
#define PREP_W_   (3*H_*H_)
#define PREP_WO_  (2*H_*H_)
#define PREP_ROW_ (R_*C_)
#define PREP_CY_  (RN_)
#define PREP_WC_  (128*K2_)
#define PREP_TOTAL_ (PREP_W_ + PREP_WO_ + PREP_ROW_ + PREP_CY_ + PREP_WC_)

__global__ void k_prep_all(
    const int* __restrict__ sop, const float* __restrict__ matrix,
    const float* w3w, const float* w3u, const float* b3w, const float* b3u,
    const float* w4w, const float* w4u, const float* b4w, const float* b4u,
    const float* w5w, const float* w5u, const float* b5w, const float* b5u,
    const float* __restrict__ wo, const float* __restrict__ wc)
{
    int i = blockIdx.x*blockDim.x + threadIdx.x;
    if (i < PREP_W_) {
        int g = i / (H_*H_);
        int rem = i - g*(H_*H_);
        int h = rem / H_, k = rem - h*H_;
        const float* ww = (g==0) ? w3w : (g==1) ? w4w : w5w;
        const float* wu = (g==0) ? w3u : (g==1) ? w4u : w5u;
        g_weff[i] = __float2half_rn(ww[h*(2*H_) + k] + ww[h*(2*H_) + H_ + k]);
        g_ucat[i] = __float2half_rn(wu[rem]);
        if (i < 3*H_) {
            int gg = i / H_, h2 = i - gg*H_;
            const float* bw = (gg==0) ? b3w : (gg==1) ? b4w : b5w;
            const float* bu = (gg==0) ? b3u : (gg==1) ? b4u : b5u;
            g_bias[i] = bw[h2] + bu[h2];
        }
    } else if (i < PREP_W_ + PREP_WO_) {
        int j = i - PREP_W_;
        int row = j >> 10, col = j & 1023;
        int dst = (col < H_) ? row*H_ + col : (row + H_)*H_ + (col - H_);
        g_wor[dst] = __float2half_rn(wo[j]);
    } else if (i < PREP_W_ + PREP_WO_ + PREP_ROW_) {
        int j = i - PREP_W_ - PREP_WO_;
        int r = j / C_, c = j - r*C_;
        g_row[j] = matrix[((size_t)sop[2*r]*NOBJ_ + sop[2*r+1])*C_ + c];
    } else if (i < PREP_W_ + PREP_WO_ + PREP_ROW_ + PREP_CY_) {
        int j = i - PREP_W_ - PREP_WO_ - PREP_ROW_;
        int r = j / NODE_, e = j - r*NODE_;
        if (e < 2) { g_coef[j] = 1.f; g_yrow[j] = r; }
        else {
            g_coef[j] = matrix[((size_t)sop[2*r]*NOBJ_ + sop[2*r+1])*C_ + (e-2)];
            g_yrow[j] = R_ + r;
        }
    } else if (i < PREP_TOTAL_) {
        int j = i - PREP_W_ - PREP_WO_ - PREP_ROW_ - PREP_CY_;
        int row = j / K2_, col = j - row*K2_;
        g_wc[j] = (row < C_) ? __float2half_rn(wc[(size_t)row*K2_ + col]) : __float2half_rn(0.f);
    }
}

__global__ void k_copy_in(const float* __restrict__ src) {
    int n2 = (RN_*H_)/2;
    __half2* dst = (__half2*)g_inp;
    const float2* s = (const float2*)src;
    for (int i = blockIdx.x*blockDim.x + threadIdx.x; i < n2; i += gridDim.x*blockDim.x) {
        float2 v = s[i];
        dst[i] = __floats2half2_rn(v.x, v.y);
    }
}

// ================= av: per-relation acc & s01 vectors ======================
__global__ void __launch_bounds__(256) k_av(const __half* __restrict__ hid) {
    __shared__ float srow[C_];
    int r = blockIdx.x;
    if (threadIdx.x < C_) srow[threadIdx.x] = g_row[r*C_ + threadIdx.x];
    __syncthreads();
    int h2i = threadIdx.x;                 // half2 index 0..255
    const __half2* hb = (const __half2*)(hid + (size_t)r*NODE_*H_);
    float2 a0 = __half22float2(hb[h2i]);
    float2 a1 = __half22float2(hb[256 + h2i]);
    float sx = a0.x + a1.x, sy = a0.y + a1.y;
    float ax = 0.f, ay = 0.f;
    #pragma unroll 3
    for (int c = 0; c < C_; ++c) {
        float rc = srow[c];
        float2 v = __half22float2(hb[(2+c)*256 + h2i]);
        ax = fmaf(rc, v.x, ax);
        ay = fmaf(rc, v.y, ay);
    }
    __half2* sa = (__half2*)g_sa;
    sa[(size_t)r*256 + h2i]        = __floats2half2_rn(ax, ay);
    sa[(size_t)(R_+r)*256 + h2i]   = __floats2half2_rn(sx, sy);
}

// ================= fp16 mma GEMM: CTA 128x128, 4 warps, warp 64x64 ==========
// BK = 64 halves per chunk; 8 chunks per K=512 term.
#define ACT_NONE 0
#define ACT_GATE 1
#define ACT_GRU  2
#define ACT_RELU 3

#define ROWB_     144                      /* bytes per smem row (64 halves + 8 pad) */
#define STG_AB    (128*ROWB_)              /* 18432 bytes per operand tile */
#define STG_BYTES (2*STG_AB)               /* 36864 */
#define SMEM_BYTES (3*STG_BYTES)           /* 110592 */

template<int ACT, int NTERMS, bool SPLITK>
__global__ void __launch_bounds__(128, 2) k_hmma(
    const __half* __restrict__ A1, int lda1, const __half* __restrict__ W1, int ldw1,
    const __half* __restrict__ A2, const __half* __restrict__ W2,   // term 2 (ld 512)
    const float* __restrict__ bias,
    const __half* __restrict__ hidin,  // GATE: f for rf; GRU: previous hidden
    const float* __restrict__ zbuf,    // GRU: zv (stride 512)
    int ycol0,
    float* __restrict__ Yco, int ldy, int nmax,   // ACT_NONE fp32 output
    __half* __restrict__ Ho)                      // half output
{
    extern __shared__ __align__(16) char smc[];
    const uint32_t smem_base = smem_u32(smc);
    const int tid  = threadIdx.x;
    const int lane = tid & 31;
    const int wid  = tid >> 5;
    const int wm   = wid >> 1, wn = wid & 1;
    const int blockRow = blockIdx.y * 128;
    const int blockCol = blockIdx.x * 128;
    const int kbeg = SPLITK ? blockIdx.z * 512 : 0;

    float acc[4][8][4];
    #pragma unroll
    for (int i = 0; i < 4; ++i)
        #pragma unroll
        for (int j = 0; j < 8; ++j)
            #pragma unroll
            for (int v = 0; v < 4; ++v) acc[i][j][v] = 0.f;

    const int mrow = tid >> 3;     // 0..15
    const int qk   = tid & 7;      // 16B quad within 64-half row

    uint32_t aoff[4], boff[4];
    {
        const int rw = lane & 7;
        const int g1 = (lane >> 3) & 1;
        const int g2 = lane >> 4;
        #pragma unroll
        for (int i = 0; i < 4; ++i)
            aoff[i] = (uint32_t)(wm*64 + i*16 + rw + g1*8)*ROWB_ + g2*16;
        #pragma unroll
        for (int jj = 0; jj < 4; ++jj)
            boff[jj] = STG_AB + (uint32_t)(wn*64 + jj*16 + rw + g2*8)*ROWB_ + g1*16;
    }

    auto load_chunk = [&](int c, int stage) {
        const int term = c >> 3;
        const int kk0  = kbeg + (c & 7) * 64;
        const __half* A = term ? A2 : A1;  const int lda = term ? 512 : lda1;
        const __half* W = term ? W2 : W1;  const int ldw = term ? 512 : ldw1;
        const __half* Ag = A + (size_t)(blockRow + mrow)*lda + kk0 + qk*8;
        const __half* Wg = W + (size_t)(blockCol + mrow)*ldw + kk0 + qk*8;
        uint32_t sa = smem_base + stage*STG_BYTES + mrow*ROWB_ + qk*16;
        uint32_t sb = sa + STG_AB;
        #pragma unroll
        for (int p = 0; p < 8; ++p) {
            cp_async16(sa + p*16*ROWB_, Ag + (size_t)p*16*lda);
            cp_async16(sb + p*16*ROWB_, Wg + (size_t)p*16*ldw);
        }
    };

    auto compute = [&](int stage) {
        const uint32_t sbase = smem_base + stage*STG_BYTES;
        #pragma unroll
        for (int s = 0; s < 4; ++s) {            // 4 x k16
            uint32_t af[4][4], bf[4][4];
            #pragma unroll
            for (int i = 0; i < 4; ++i)   ldsm4(af[i],  sbase + aoff[i]  + s*32);
            #pragma unroll
            for (int jj = 0; jj < 4; ++jj) ldsm4(bf[jj], sbase + boff[jj] + s*32);
            #pragma unroll
            for (int i = 0; i < 4; ++i)
                #pragma unroll
                for (int jj = 0; jj < 4; ++jj) {
                    mma_f16(acc[i][2*jj],   af[i], &bf[jj][0]);
                    mma_f16(acc[i][2*jj+1], af[i], &bf[jj][2]);
                }
        }
    };

    const int NCH = 8*NTERMS;
    load_chunk(0, 0); CP_COMMIT();
    load_chunk(1, 1); CP_COMMIT();

    int stage_n = 2;
    for (int c = 0; c < NCH; ++c) {
        CP_WAIT(1);
        __syncthreads();
        if (c + 2 < NCH) load_chunk(c + 2, stage_n);
        CP_COMMIT();
        int stage_c = stage_n + 1; if (stage_c >= 3) stage_c -= 3;
        compute(stage_c);
        stage_n = stage_c;
    }
    CP_WAIT(0);

    // ---- epilogue
    const size_t zoff = SPLITK ? (size_t)blockIdx.z * (R_*C_) : 0;
    #pragma unroll
    for (int i = 0; i < 4; ++i) {
        const int r0 = blockRow + wm*64 + i*16 + (lane >> 2);
        float cf0 = 0.f, cf1 = 0.f;
        const float *y0p = nullptr, *y1p = nullptr;
        if (ACT == ACT_GATE || ACT == ACT_GRU) {
            cf0 = g_coef[r0];     y0p = g_Y + (size_t)g_yrow[r0]*1536   + ycol0;
            cf1 = g_coef[r0+8];   y1p = g_Y + (size_t)g_yrow[r0+8]*1536 + ycol0;
        }
        #pragma unroll
        for (int j = 0; j < 8; ++j) {
            const int gc = blockCol + wn*64 + j*8 + (lane & 3)*2;
            float v0 = acc[i][j][0];
            float v1 = acc[i][j][1];
            float v2 = acc[i][j][2];
            float v3 = acc[i][j][3];
            if (ACT != ACT_NONE) {
                float2 bs = *(const float2*)&bias[gc];
                v0 += bs.x; v1 += bs.y; v2 += bs.x; v3 += bs.y;
            }
            if (ACT == ACT_GATE || ACT == ACT_GRU) {
                float2 y0 = *(const float2*)&y0p[gc];
                float2 y1 = *(const float2*)&y1p[gc];
                v0 = fmaf(cf0, y0.x, v0); v1 = fmaf(cf0, y0.y, v1);
                v2 = fmaf(cf1, y1.x, v2); v3 = fmaf(cf1, y1.y, v3);
            }
            if (ACT == ACT_NONE) {
                if (SPLITK) {
                    // ldy (=51) is odd -> scalar stores only (alignment!)
                    if (gc < nmax) {
                        Yco[zoff + (size_t)r0*ldy + gc]     = v0;
                        Yco[zoff + (size_t)(r0+8)*ldy + gc] = v2;
                    }
                    if (gc + 1 < nmax) {
                        Yco[zoff + (size_t)r0*ldy + gc + 1]     = v1;
                        Yco[zoff + (size_t)(r0+8)*ldy + gc + 1] = v3;
                    }
                } else {
                    *(float2*)&Yco[(size_t)r0*ldy + gc]     = make_float2(v0, v1);
                    *(float2*)&Yco[(size_t)(r0+8)*ldy + gc] = make_float2(v2, v3);
                }
            } else if (ACT == ACT_GATE) {
                float s0 = 1.f/(1.f+__expf(-v0)), s1 = 1.f/(1.f+__expf(-v1));
                float s2 = 1.f/(1.f+__expf(-v2)), s3 = 1.f/(1.f+__expf(-v3));
                if (gc < 512) {   // z half -> fp32 z buffer
                    *(float2*)&g_z[(size_t)r0*512 + gc]     = make_float2(s0, s1);
                    *(float2*)&g_z[(size_t)(r0+8)*512 + gc] = make_float2(s2, s3);
                } else {          // r half -> rf = half(r * f)
                    const int hc = gc - 512;
                    float2 f0 = __half22float2(*(const __half2*)&hidin[(size_t)r0*512 + hc]);
                    float2 f1 = __half22float2(*(const __half2*)&hidin[(size_t)(r0+8)*512 + hc]);
                    *(__half2*)&g_rf[(size_t)r0*512 + hc]     = __floats2half2_rn(s0*f0.x, s1*f0.y);
                    *(__half2*)&g_rf[(size_t)(r0+8)*512 + hc] = __floats2half2_rn(s2*f1.x, s3*f1.y);
                }
            } else if (ACT == ACT_RELU) {
                *(__half2*)&Ho[(size_t)r0*512 + gc]     = __floats2half2_rn(fmaxf(v0,0.f), fmaxf(v1,0.f));
                *(__half2*)&Ho[(size_t)(r0+8)*512 + gc] = __floats2half2_rn(fmaxf(v2,0.f), fmaxf(v3,0.f));
            } else {  // GRU: h' = (1-z)*f + z*tanh(v)
                float2 z0 = *(const float2*)&zbuf[(size_t)r0*512 + gc];
                float2 z1 = *(const float2*)&zbuf[(size_t)(r0+8)*512 + gc];
                float2 f0 = __half22float2(*(const __half2*)&hidin[(size_t)r0*512 + gc]);
                float2 f1 = __half22float2(*(const __half2*)&hidin[(size_t)(r0+8)*512 + gc]);
                float o0 = (1.f-z0.x)*f0.x + z0.x*tanhf(v0);
                float o1 = (1.f-z0.y)*f0.y + z0.y*tanhf(v1);
                float o2 = (1.f-z1.x)*f1.x + z1.x*tanhf(v2);
                float o3 = (1.f-z1.y)*f1.y + z1.y*tanhf(v3);
                *(__half2*)&Ho[(size_t)r0*512 + gc]     = __floats2half2_rn(o0, o1);
                *(__half2*)&Ho[(size_t)(r0+8)*512 + gc] = __floats2half2_rn(o2, o3);
            }
        }
    }
}

__global__ void k_reduce(const float* __restrict__ bc, float* __restrict__ out) {
    int i = blockIdx.x*blockDim.x + threadIdx.x;
    if (i >= R_*C_) return;
    float s = bc[i % C_];
    for (int z = 0; z < SPLITS_; ++z) s += g_part[(size_t)z*(R_*C_) + i];
    out[i] = s;
}

// ================= launch =================
extern "C" void kernel_launch(void* const* d_in, const int* in_sizes, int n_in,
                              void* d_out, int out_size) {
    const int*   sop    = (const int*)  d_in[1];
    const float* input  = (const float*)d_in[2];
    const float* matrix = (const float*)d_in[4];
    const float* w3w = (const float*)d_in[5];  const float* b3w = (const float*)d_in[6];
    const float* w3u = (const float*)d_in[7];  const float* b3u = (const float*)d_in[8];
    const float* w4w = (const float*)d_in[9];  const float* b4w = (const float*)d_in[10];
    const float* w4u = (const float*)d_in[11]; const float* b4u = (const float*)d_in[12];
    const float* w5w = (const float*)d_in[13]; const float* b5w = (const float*)d_in[14];
    const float* w5u = (const float*)d_in[15]; const float* b5u = (const float*)d_in[16];
    const float* wo  = (const float*)d_in[17]; const float* bo  = (const float*)d_in[18];
    const float* wc  = (const float*)d_in[19]; const float* bc  = (const float*)d_in[20];
    float* out = (float*)d_out;

    __half *p_h0, *p_h1, *p_inp, *p_sa, *p_rf, *p_out, *p_weff, *p_ucat, *p_wor, *p_wc;
    float  *p_Y, *p_z, *p_bias, *p_part;
    cudaGetSymbolAddress((void**)&p_h0,   g_hid0);
    cudaGetSymbolAddress((void**)&p_h1,   g_hid1);
    cudaGetSymbolAddress((void**)&p_inp,  g_inp);
    cudaGetSymbolAddress((void**)&p_sa,   g_sa);
    cudaGetSymbolAddress((void**)&p_rf,   g_rf);
    cudaGetSymbolAddress((void**)&p_out,  g_out);
    cudaGetSymbolAddress((void**)&p_weff, g_weff);
    cudaGetSymbolAddress((void**)&p_ucat, g_ucat);
    cudaGetSymbolAddress((void**)&p_wor,  g_wor);
    cudaGetSymbolAddress((void**)&p_wc,   g_wc);
    cudaGetSymbolAddress((void**)&p_Y,    g_Y);
    cudaGetSymbolAddress((void**)&p_z,    g_z);
    cudaGetSymbolAddress((void**)&p_bias, g_bias);
    cudaGetSymbolAddress((void**)&p_part, g_part);

    cudaFuncSetAttribute(k_hmma<ACT_NONE,1,false>, cudaFuncAttributeMaxDynamicSharedMemorySize, SMEM_BYTES);
    cudaFuncSetAttribute(k_hmma<ACT_NONE,1,true>,  cudaFuncAttributeMaxDynamicSharedMemorySize, SMEM_BYTES);
    cudaFuncSetAttribute(k_hmma<ACT_GATE,1,false>, cudaFuncAttributeMaxDynamicSharedMemorySize, SMEM_BYTES);
    cudaFuncSetAttribute(k_hmma<ACT_GRU,1,false>,  cudaFuncAttributeMaxDynamicSharedMemorySize, SMEM_BYTES);
    cudaFuncSetAttribute(k_hmma<ACT_RELU,2,false>, cudaFuncAttributeMaxDynamicSharedMemorySize, SMEM_BYTES);

    k_prep_all<<<(PREP_TOTAL_ + 255)/256, 256>>>(sop, matrix,
        w3w, w3u, b3w, b3u, w4w, w4u, b4w, b4u, w5w, w5u, b5w, b5u, wo, wc);
    k_copy_in<<<2048, 256>>>(input);

    dim3 gY   (1536/128, 2*R_/128);   // 12 x 32
    dim3 gGate(1024/128, RN_/128);    // 8 x 848
    dim3 gHv  (512/128,  RN_/128);    // 4 x 848
    dim3 gFin (1, R_/128, SPLITS_);   // 1 x 16 x 53

    __half* hin = p_inp;              // t=0 hidden IS the half input
    __half* houts[3] = {p_h0, p_h1, p_h0};
    for (int t = 0; t < T_; ++t) {
        __half* hout = houts[t];
        k_av<<<R_, 256>>>(hin);
        // Y = [acc; s01] @ [W3e;W4e;W5e]^T   (4096 x 1536, K=512, fp32 out)
        k_hmma<ACT_NONE,1,false><<<gY, 128, SMEM_BYTES>>>(
            p_sa, 512, p_weff, 512, nullptr, nullptr,
            nullptr, nullptr, nullptr, 0, p_Y, 1536, 1536, nullptr);
        // gates: sigmoid(fh@[w3u;w4u]^T + coef*Y[:,0:1024] + bias) -> z (f32) | rf (half)
        k_hmma<ACT_GATE,1,false><<<gGate, 128, SMEM_BYTES>>>(
            hin, 512, p_ucat, 512, nullptr, nullptr,
            p_bias, hin, nullptr, 0, nullptr, 0, 0, nullptr);
        // hidden' = (1-z)*f + z*tanh(rf@w5u^T + coef*Y[:,1024:1536] + b5)
        k_hmma<ACT_GRU,1,false><<<gHv, 128, SMEM_BYTES>>>(
            p_rf, 512, p_ucat + 2*H_*H_, 512, nullptr, nullptr,
            p_bias + 2*H_, hin, p_z, 1024, nullptr, 0, 0, hout);
        hin = hout;
    }

    // out = relu(fh@wo[:, :H].T + input@wo[:, H:].T + bo)  -> half
    k_hmma<ACT_RELU,2,false><<<gHv, 128, SMEM_BYTES>>>(
        hin, 512, p_wor, 512, p_inp, p_wor + H_*H_,
        bo, nullptr, nullptr, 0, nullptr, 0, 0, p_out);

    // rel_dists partials: out.reshape(R, 27136) @ wc_pad^T   (split-K fp16 mma)
    k_hmma<ACT_NONE,1,true><<<gFin, 128, SMEM_BYTES>>>(
        p_out, K2_, p_wc, K2_, nullptr, nullptr,
        nullptr, nullptr, nullptr, 0, p_part, C_, C_, nullptr);
    k_reduce<<<(R_*C_ + 255)/256, 256>>>(bc, out);
}

// round 9
// speedup vs baseline: 9.6223x; 1.2592x over previous
#include <cuda_runtime.h>
#include <cuda_fp16.h>
#include <math.h>
#include <stdint.h>

#define R_    2048
#define NODE_ 53
#define H_    512
#define C_    51
#define NOBJ_ 151
#define T_    3
#define RN_   (R_*NODE_)      /* 108544 */
#define K2_   (NODE_*512)     /* 27136  */
#define SPLITS_ 53

// ================= helpers =================
__device__ __forceinline__ void mma_f16(float* d, const uint32_t* a, const uint32_t* b) {
    asm volatile(
        "mma.sync.aligned.m16n8k16.row.col.f32.f16.f16.f32 "
        "{%0,%1,%2,%3}, {%4,%5,%6,%7}, {%8,%9}, {%0,%1,%2,%3};\n"
        : "+f"(d[0]), "+f"(d[1]), "+f"(d[2]), "+f"(d[3])
        : "r"(a[0]), "r"(a[1]), "r"(a[2]), "r"(a[3]), "r"(b[0]), "r"(b[1]));
}
__device__ __forceinline__ void ldsm4(uint32_t* r, uint32_t addr) {
    asm volatile("ldmatrix.sync.aligned.m8n8.x4.shared.b16 {%0,%1,%2,%3}, [%4];"
        : "=r"(r[0]), "=r"(r[1]), "=r"(r[2]), "=r"(r[3]) : "r"(addr));
}
__device__ __forceinline__ uint32_t smem_u32(const void* p) {
    uint32_t a;
    asm("{ .reg .u64 t; cvta.to.shared.u64 t, %1; cvt.u32.u64 %0, t; }" : "=r"(a) : "l"(p));
    return a;
}
__device__ __forceinline__ void cp_async16(uint32_t s, const void* g) {
    asm volatile("cp.async.cg.shared.global [%0], [%1], 16;" :: "r"(s), "l"(g));
}
#define CP_COMMIT() asm volatile("cp.async.commit_group;" ::: "memory")
#define CP_WAIT(n)  asm volatile("cp.async.wait_group %0;" :: "n"(n) : "memory")

// ================= scratch =================
__device__ __half g_hid0 [RN_*H_];
__device__ __half g_hid1 [RN_*H_];
__device__ __half g_inp  [RN_*H_];
__device__ __half g_sa   [2*R_*H_];
__device__ __half g_rf   [RN_*H_];
__device__ __half g_out  [RN_*H_];
__device__ __half g_weff [3*H_*H_];
__device__ __half g_ucat [3*H_*H_];
__device__ __half g_wor  [2*H_*H_];
__device__ __half g_wc   [128*K2_];
__device__ float  g_z    [RN_*H_];
__device__ float  g_Y    [2*R_*3*H_];
__device__ float  g_bias [3*H_];
__device__ float  g_row  [R_*C_];
__device__ float  g_coef [RN_];
__device__ int    g_yrow [RN_];
__device__ float  g_part [SPLITS_*R_*C_];

// ================= combined prep =================
#define PREP_W_   (3*H_*H_)
#define PREP_WO_  (2*H_*H_)
#define PREP_ROW_ (R_*C_)
#define PREP_CY_  (RN_)
#define PREP_WC_  (128*K2_)
#define PREP_TOTAL_ (PREP_W_ + PREP_WO_ + PREP_ROW_ + PREP_CY_ + PREP_WC_)

__global__ void k_prep_all(
    const int* __restrict__ sop, const float* __restrict__ matrix,
    const float* w3w, const float* w3u, const float* b3w, const float* b3u,
    const float* w4w, const float* w4u, const float* b4w, const float* b4u,
    const float* w5w, const float* w5u, const float* b5w, const float* b5u,
    const float* __restrict__ wo, const float* __restrict__ wc)
{
    int i = blockIdx.x*blockDim.x + threadIdx.x;
    if (i < PREP_W_) {
        int g = i / (H_*H_);
        int rem = i - g*(H_*H_);
        int h = rem / H_, k = rem - h*H_;
        const float* ww = (g==0) ? w3w : (g==1) ? w4w : w5w;
        const float* wu = (g==0) ? w3u : (g==1) ? w4u : w5u;
        g_weff[i] = __float2half_rn(ww[h*(2*H_) + k] + ww[h*(2*H_) + H_ + k]);
        g_ucat[i] = __float2half_rn(wu[rem]);
        if (i < 3*H_) {
            int gg = i / H_, h2 = i - gg*H_;
            const float* bw = (gg==0) ? b3w : (gg==1) ? b4w : b5w;
            const float* bu = (gg==0) ? b3u : (gg==1) ? b4u : b5u;
            g_bias[i] = bw[h2] + bu[h2];
        }
    } else if (i < PREP_W_ + PREP_WO_) {
        int j = i - PREP_W_;
        int row = j >> 10, col = j & 1023;
        int dst = (col < H_) ? row*H_ + col : (row + H_)*H_ + (col - H_);
        g_wor[dst] = __float2half_rn(wo[j]);
    } else if (i < PREP_W_ + PREP_WO_ + PREP_ROW_) {
        int j = i - PREP_W_ - PREP_WO_;
        int r = j / C_, c = j - r*C_;
        g_row[j] = matrix[((size_t)sop[2*r]*NOBJ_ + sop[2*r+1])*C_ + c];
    } else if (i < PREP_W_ + PREP_WO_ + PREP_ROW_ + PREP_CY_) {
        int j = i - PREP_W_ - PREP_WO_ - PREP_ROW_;
        int r = j / NODE_, e = j - r*NODE_;
        if (e < 2) { g_coef[j] = 1.f; g_yrow[j] = r; }
        else {
            g_coef[j] = matrix[((size_t)sop[2*r]*NOBJ_ + sop[2*r+1])*C_ + (e-2)];
            g_yrow[j] = R_ + r;
        }
    } else if (i < PREP_TOTAL_) {
        int j = i - PREP_W_ - PREP_WO_ - PREP_ROW_ - PREP_CY_;
        int row = j / K2_, col = j - row*K2_;
        g_wc[j] = (row < C_) ? __float2half_rn(wc[(size_t)row*K2_ + col]) : __float2half_rn(0.f);
    }
}

__global__ void k_copy_in(const float* __restrict__ src) {
    int n2 = (RN_*H_)/2;
    __half2* dst = (__half2*)g_inp;
    const float2* s = (const float2*)src;
    for (int i = blockIdx.x*blockDim.x + threadIdx.x; i < n2; i += gridDim.x*blockDim.x) {
        float2 v = s[i];
        dst[i] = __floats2half2_rn(v.x, v.y);
    }
}

// ================= av =================
__global__ void __launch_bounds__(256) k_av(const __half* __restrict__ hid) {
    __shared__ float srow[C_];
    int r = blockIdx.x;
    if (threadIdx.x < C_) srow[threadIdx.x] = g_row[r*C_ + threadIdx.x];
    __syncthreads();
    int h2i = threadIdx.x;
    const __half2* hb = (const __half2*)(hid + (size_t)r*NODE_*H_);
    float2 a0 = __half22float2(hb[h2i]);
    float2 a1 = __half22float2(hb[256 + h2i]);
    float sx = a0.x + a1.x, sy = a0.y + a1.y;
    float ax = 0.f, ay = 0.f;
    #pragma unroll 3
    for (int c = 0; c < C_; ++c) {
        float rc = srow[c];
        float2 v = __half22float2(hb[(2+c)*256 + h2i]);
        ax = fmaf(rc, v.x, ax);
        ay = fmaf(rc, v.y, ay);
    }
    __half2* sa = (__half2*)g_sa;
    sa[(size_t)r*256 + h2i]        = __floats2half2_rn(ax, ay);
    sa[(size_t)(R_+r)*256 + h2i]   = __floats2half2_rn(sx, sy);
}

// ===== fp16 mma GEMM: CTA 128x128, 8 warps (2x4), warp tile 64x32 ===========
#define ACT_NONE 0
#define ACT_GATE 1
#define ACT_GRU  2
#define ACT_RELU 3

#define ROWB_     144
#define STG_AB    (128*ROWB_)              /* 18432 */
#define STG_BYTES (2*STG_AB)               /* 36864 */
#define SMEM_BYTES (3*STG_BYTES)           /* 110592 */

template<int ACT, int NTERMS, bool SPLITK>
__global__ void __launch_bounds__(256, 2) k_hmma(
    const __half* __restrict__ A1, int lda1, const __half* __restrict__ W1, int ldw1,
    const __half* __restrict__ A2, const __half* __restrict__ W2,
    const float* __restrict__ bias,
    const __half* __restrict__ hidin,
    const float* __restrict__ zbuf,
    int ycol0,
    float* __restrict__ Yco, int ldy, int nmax,
    __half* __restrict__ Ho)
{
    extern __shared__ __align__(16) char smc[];
    const uint32_t smem_base = smem_u32(smc);
    const int tid  = threadIdx.x;
    const int lane = tid & 31;
    const int wid  = tid >> 5;            // 0..7
    const int wm   = wid >> 2;            // 0..1  (64-row strip)
    const int wn   = wid & 3;             // 0..3  (32-col strip)
    const int blockRow = blockIdx.y * 128;
    const int blockCol = blockIdx.x * 128;
    const int kbeg = SPLITK ? blockIdx.z * 512 : 0;

    float acc[4][4][4];
    #pragma unroll
    for (int i = 0; i < 4; ++i)
        #pragma unroll
        for (int j = 0; j < 4; ++j)
            #pragma unroll
            for (int v = 0; v < 4; ++v) acc[i][j][v] = 0.f;

    const int mrow = tid >> 3;     // 0..31
    const int qk   = tid & 7;

    uint32_t aoff[4], boff[2];
    {
        const int rw = lane & 7;
        const int g1 = (lane >> 3) & 1;
        const int g2 = lane >> 4;
        #pragma unroll
        for (int i = 0; i < 4; ++i)
            aoff[i] = (uint32_t)(wm*64 + i*16 + rw + g1*8)*ROWB_ + g2*16;
        #pragma unroll
        for (int jj = 0; jj < 2; ++jj)
            boff[jj] = STG_AB + (uint32_t)(wn*32 + jj*16 + rw + g2*8)*ROWB_ + g1*16;
    }

    auto load_chunk = [&](int c, int stage) {
        const int term = c >> 3;
        const int kk0  = kbeg + (c & 7) * 64;
        const __half* A = term ? A2 : A1;  const int lda = term ? 512 : lda1;
        const __half* W = term ? W2 : W1;  const int ldw = term ? 512 : ldw1;
        const __half* Ag = A + (size_t)(blockRow + mrow)*lda + kk0 + qk*8;
        const __half* Wg = W + (size_t)(blockCol + mrow)*ldw + kk0 + qk*8;
        uint32_t sa = smem_base + stage*STG_BYTES + mrow*ROWB_ + qk*16;
        uint32_t sb = sa + STG_AB;
        #pragma unroll
        for (int p = 0; p < 4; ++p) {
            cp_async16(sa + p*32*ROWB_, Ag + (size_t)p*32*lda);
            cp_async16(sb + p*32*ROWB_, Wg + (size_t)p*32*ldw);
        }
    };

    auto compute = [&](int stage) {
        const uint32_t sbase = smem_base + stage*STG_BYTES;
        #pragma unroll
        for (int s = 0; s < 4; ++s) {
            uint32_t af[4][4], bf[2][4];
            #pragma unroll
            for (int i = 0; i < 4; ++i)   ldsm4(af[i],  sbase + aoff[i]  + s*32);
            #pragma unroll
            for (int jj = 0; jj < 2; ++jj) ldsm4(bf[jj], sbase + boff[jj] + s*32);
            #pragma unroll
            for (int i = 0; i < 4; ++i)
                #pragma unroll
                for (int jj = 0; jj < 2; ++jj) {
                    mma_f16(acc[i][2*jj],   af[i], &bf[jj][0]);
                    mma_f16(acc[i][2*jj+1], af[i], &bf[jj][2]);
                }
        }
    };

    const int NCH = 8*NTERMS;
    load_chunk(0, 0); CP_COMMIT();
    load_chunk(1, 1); CP_COMMIT();

    int stage_n = 2;
    for (int c = 0; c < NCH; ++c) {
        CP_WAIT(1);
        __syncthreads();
        if (c + 2 < NCH) load_chunk(c + 2, stage_n);
        CP_COMMIT();
        int stage_c = stage_n + 1; if (stage_c >= 3) stage_c -= 3;
        compute(stage_c);
        stage_n = stage_c;
    }
    CP_WAIT(0);

    // ---- epilogue
    const size_t zoff = SPLITK ? (size_t)blockIdx.z * (R_*C_) : 0;
    #pragma unroll
    for (int i = 0; i < 4; ++i) {
        const int r0 = blockRow + wm*64 + i*16 + (lane >> 2);
        float cf0 = 0.f, cf1 = 0.f;
        const float *y0p = nullptr, *y1p = nullptr;
        if (ACT == ACT_GATE || ACT == ACT_GRU) {
            cf0 = g_coef[r0];     y0p = g_Y + (size_t)g_yrow[r0]*1536   + ycol0;
            cf1 = g_coef[r0+8];   y1p = g_Y + (size_t)g_yrow[r0+8]*1536 + ycol0;
        }
        #pragma unroll
        for (int j = 0; j < 4; ++j) {
            const int gc = blockCol + wn*32 + j*8 + (lane & 3)*2;
            float v0 = acc[i][j][0];
            float v1 = acc[i][j][1];
            float v2 = acc[i][j][2];
            float v3 = acc[i][j][3];
            if (ACT != ACT_NONE) {
                float2 bs = *(const float2*)&bias[gc];
                v0 += bs.x; v1 += bs.y; v2 += bs.x; v3 += bs.y;
            }
            if (ACT == ACT_GATE || ACT == ACT_GRU) {
                float2 y0 = *(const float2*)&y0p[gc];
                float2 y1 = *(const float2*)&y1p[gc];
                v0 = fmaf(cf0, y0.x, v0); v1 = fmaf(cf0, y0.y, v1);
                v2 = fmaf(cf1, y1.x, v2); v3 = fmaf(cf1, y1.y, v3);
            }
            if (ACT == ACT_NONE) {
                if (SPLITK) {
                    if (gc < nmax) {
                        Yco[zoff + (size_t)r0*ldy + gc]     = v0;
                        Yco[zoff + (size_t)(r0+8)*ldy + gc] = v2;
                    }
                    if (gc + 1 < nmax) {
                        Yco[zoff + (size_t)r0*ldy + gc + 1]     = v1;
                        Yco[zoff + (size_t)(r0+8)*ldy + gc + 1] = v3;
                    }
                } else {
                    *(float2*)&Yco[(size_t)r0*ldy + gc]     = make_float2(v0, v1);
                    *(float2*)&Yco[(size_t)(r0+8)*ldy + gc] = make_float2(v2, v3);
                }
            } else if (ACT == ACT_GATE) {
                float s0 = 1.f/(1.f+__expf(-v0)), s1 = 1.f/(1.f+__expf(-v1));
                float s2 = 1.f/(1.f+__expf(-v2)), s3 = 1.f/(1.f+__expf(-v3));
                if (gc < 512) {
                    *(float2*)&g_z[(size_t)r0*512 + gc]     = make_float2(s0, s1);
                    *(float2*)&g_z[(size_t)(r0+8)*512 + gc] = make_float2(s2, s3);
                } else {
                    const int hc = gc - 512;
                    float2 f0 = __half22float2(*(const __half2*)&hidin[(size_t)r0*512 + hc]);
                    float2 f1 = __half22float2(*(const __half2*)&hidin[(size_t)(r0+8)*512 + hc]);
                    *(__half2*)&g_rf[(size_t)r0*512 + hc]     = __floats2half2_rn(s0*f0.x, s1*f0.y);
                    *(__half2*)&g_rf[(size_t)(r0+8)*512 + hc] = __floats2half2_rn(s2*f1.x, s3*f1.y);
                }
            } else if (ACT == ACT_RELU) {
                *(__half2*)&Ho[(size_t)r0*512 + gc]     = __floats2half2_rn(fmaxf(v0,0.f), fmaxf(v1,0.f));
                *(__half2*)&Ho[(size_t)(r0+8)*512 + gc] = __floats2half2_rn(fmaxf(v2,0.f), fmaxf(v3,0.f));
            } else {  // GRU
                float2 z0 = *(const float2*)&zbuf[(size_t)r0*512 + gc];
                float2 z1 = *(const float2*)&zbuf[(size_t)(r0+8)*512 + gc];
                float2 f0 = __half22float2(*(const __half2*)&hidin[(size_t)r0*512 + gc]);
                float2 f1 = __half22float2(*(const __half2*)&hidin[(size_t)(r0+8)*512 + gc]);
                float o0 = (1.f-z0.x)*f0.x + z0.x*tanhf(v0);
                float o1 = (1.f-z0.y)*f0.y + z0.y*tanhf(v1);
                float o2 = (1.f-z1.x)*f1.x + z1.x*tanhf(v2);
                float o3 = (1.f-z1.y)*f1.y + z1.y*tanhf(v3);
                *(__half2*)&Ho[(size_t)r0*512 + gc]     = __floats2half2_rn(o0, o1);
                *(__half2*)&Ho[(size_t)(r0+8)*512 + gc] = __floats2half2_rn(o2, o3);
            }
        }
    }
}

__global__ void k_reduce(const float* __restrict__ bc, float* __restrict__ out) {
    int i = blockIdx.x*blockDim.x + threadIdx.x;
    if (i >= R_*C_) return;
    float s = bc[i % C_];
    for (int z = 0; z < SPLITS_; ++z) s += g_part[(size_t)z*(R_*C_) + i];
    out[i] = s;
}

// ================= launch =================
extern "C" void kernel_launch(void* const* d_in, const int* in_sizes, int n_in,
                              void* d_out, int out_size) {
    const int*   sop    = (const int*)  d_in[1];
    const float* input  = (const float*)d_in[2];
    const float* matrix = (const float*)d_in[4];
    const float* w3w = (const float*)d_in[5];  const float* b3w = (const float*)d_in[6];
    const float* w3u = (const float*)d_in[7];  const float* b3u = (const float*)d_in[8];
    const float* w4w = (const float*)d_in[9];  const float* b4w = (const float*)d_in[10];
    const float* w4u = (const float*)d_in[11]; const float* b4u = (const float*)d_in[12];
    const float* w5w = (const float*)d_in[13]; const float* b5w = (const float*)d_in[14];
    const float* w5u = (const float*)d_in[15]; const float* b5u = (const float*)d_in[16];
    const float* wo  = (const float*)d_in[17]; const float* bo  = (const float*)d_in[18];
    const float* wc  = (const float*)d_in[19]; const float* bc  = (const float*)d_in[20];
    float* out = (float*)d_out;

    __half *p_h0, *p_h1, *p_inp, *p_sa, *p_rf, *p_out, *p_weff, *p_ucat, *p_wor, *p_wc;
    float  *p_Y, *p_z, *p_bias, *p_part;
    cudaGetSymbolAddress((void**)&p_h0,   g_hid0);
    cudaGetSymbolAddress((void**)&p_h1,   g_hid1);
    cudaGetSymbolAddress((void**)&p_inp,  g_inp);
    cudaGetSymbolAddress((void**)&p_sa,   g_sa);
    cudaGetSymbolAddress((void**)&p_rf,   g_rf);
    cudaGetSymbolAddress((void**)&p_out,  g_out);
    cudaGetSymbolAddress((void**)&p_weff, g_weff);
    cudaGetSymbolAddress((void**)&p_ucat, g_ucat);
    cudaGetSymbolAddress((void**)&p_wor,  g_wor);
    cudaGetSymbolAddress((void**)&p_wc,   g_wc);
    cudaGetSymbolAddress((void**)&p_Y,    g_Y);
    cudaGetSymbolAddress((void**)&p_z,    g_z);
    cudaGetSymbolAddress((void**)&p_bias, g_bias);
    cudaGetSymbolAddress((void**)&p_part, g_part);

    cudaFuncSetAttribute(k_hmma<ACT_NONE,1,false>, cudaFuncAttributeMaxDynamicSharedMemorySize, SMEM_BYTES);
    cudaFuncSetAttribute(k_hmma<ACT_NONE,1,true>,  cudaFuncAttributeMaxDynamicSharedMemorySize, SMEM_BYTES);
    cudaFuncSetAttribute(k_hmma<ACT_GATE,1,false>, cudaFuncAttributeMaxDynamicSharedMemorySize, SMEM_BYTES);
    cudaFuncSetAttribute(k_hmma<ACT_GRU,1,false>,  cudaFuncAttributeMaxDynamicSharedMemorySize, SMEM_BYTES);
    cudaFuncSetAttribute(k_hmma<ACT_RELU,2,false>, cudaFuncAttributeMaxDynamicSharedMemorySize, SMEM_BYTES);

    k_prep_all<<<(PREP_TOTAL_ + 255)/256, 256>>>(sop, matrix,
        w3w, w3u, b3w, b3u, w4w, w4u, b4w, b4u, w5w, w5u, b5w, b5u, wo, wc);
    k_copy_in<<<2048, 256>>>(input);

    dim3 gY   (1536/128, 2*R_/128);   // 12 x 32
    dim3 gGate(1024/128, RN_/128);    // 8 x 848
    dim3 gHv  (512/128,  RN_/128);    // 4 x 848
    dim3 gFin (1, R_/128, SPLITS_);   // 1 x 16 x 53

    __half* hin = p_inp;
    __half* houts[3] = {p_h0, p_h1, p_h0};
    for (int t = 0; t < T_; ++t) {
        __half* hout = houts[t];
        k_av<<<R_, 256>>>(hin);
        k_hmma<ACT_NONE,1,false><<<gY, 256, SMEM_BYTES>>>(
            p_sa, 512, p_weff, 512, nullptr, nullptr,
            nullptr, nullptr, nullptr, 0, p_Y, 1536, 1536, nullptr);
        k_hmma<ACT_GATE,1,false><<<gGate, 256, SMEM_BYTES>>>(
            hin, 512, p_ucat, 512, nullptr, nullptr,
            p_bias, hin, nullptr, 0, nullptr, 0, 0, nullptr);
        k_hmma<ACT_GRU,1,false><<<gHv, 256, SMEM_BYTES>>>(
            p_rf, 512, p_ucat + 2*H_*H_, 512, nullptr, nullptr,
            p_bias + 2*H_, hin, p_z, 1024, nullptr, 0, 0, hout);
        hin = hout;
    }

    k_hmma<ACT_RELU,2,false><<<gHv, 256, SMEM_BYTES>>>(
        hin, 512, p_wor, 512, p_inp, p_wor + H_*H_,
        bo, nullptr, nullptr, 0, nullptr, 0, 0, p_out);

    k_hmma<ACT_NONE,1,true><<<gFin, 256, SMEM_BYTES>>>(
        p_out, K2_, p_wc, K2_, nullptr, nullptr,
        nullptr, nullptr, nullptr, 0, p_part, C_, C_, nullptr);
    k_reduce<<<(R_*C_ + 255)/256, 256>>>(bc, out);
}